// round 1
// baseline (speedup 1.0000x reference)
#include <cuda_runtime.h>
#include <math.h>

// ---------------------------------------------------------------------------
// Problem constants
// ---------------------------------------------------------------------------
#define B_  16
#define C_  512
#define N_  1024
#define HW  32
#define PITCH 132   // smem pitch (floats) to dodge bank conflicts, 16B-aligned rows

static constexpr size_t TSZ  = (size_t)B_ * C_ * N_;        // 8,388,608 elems per tensor
static constexpr size_t WTSZ = (size_t)9 * C_ * (2 * C_);   // 4,718,592 transposed conv weights

// ---------------------------------------------------------------------------
// Scratch (static device globals; no allocation anywhere)
// ---------------------------------------------------------------------------
__device__ float g_S [(size_t)B_ * N_ * N_];   // attention scores / softmax (67 MB)
__device__ float g_O1[TSZ], g_O2[TSZ];         // attention outputs
__device__ float g_a1[TSZ], g_a2[TSZ], g_a3[TSZ];
__device__ float g_ex[TSZ], g_q [TSZ], g_q1[TSZ];  // recurrent states
__device__ float g_r [TSZ], g_u [TSZ], g_c [TSZ];  // GRU intermediates
__device__ float g_wf[WTSZ], g_wo[WTSZ];       // conv weights transposed [tap][co][ci]

// ---------------------------------------------------------------------------
// Shared 128x128 tile micro-kernel: 256 threads, 8x8 per thread, BK=8
// ---------------------------------------------------------------------------
__device__ __forceinline__ void mac_step(const float (*As)[PITCH], const float (*Bs)[PITCH],
                                         int tr, int tc, float (&acc)[8][8]) {
#pragma unroll
    for (int k = 0; k < 8; ++k) {
        float4 a0 = *(const float4*)&As[k][tr];
        float4 a1 = *(const float4*)&As[k][tr + 4];
        float4 b0 = *(const float4*)&Bs[k][tc];
        float4 b1 = *(const float4*)&Bs[k][tc + 4];
        float ar[8] = {a0.x, a0.y, a0.z, a0.w, a1.x, a1.y, a1.z, a1.w};
        float br[8] = {b0.x, b0.y, b0.z, b0.w, b1.x, b1.y, b1.z, b1.w};
#pragma unroll
        for (int i = 0; i < 8; ++i)
#pragma unroll
            for (int j = 0; j < 8; ++j)
                acc[i][j] = fmaf(ar[i], br[j], acc[i][j]);
    }
}

#define ZERO_ACC(acc)                         \
    float acc[8][8];                          \
    _Pragma("unroll")                         \
    for (int i = 0; i < 8; ++i)               \
        _Pragma("unroll")                     \
        for (int j = 0; j < 8; ++j) acc[i][j] = 0.f;

// ---------------------------------------------------------------------------
// Attention scores: S[b,n,m] = sum_c E[b,c,n] * Q[b,c,m]   (TN GEMM, K=512)
// grid (8, 8, 16)
// ---------------------------------------------------------------------------
__global__ void __launch_bounds__(256) k_scores(const float* __restrict__ E,
                                                const float* __restrict__ Q,
                                                float* __restrict__ S) {
    int b = blockIdx.z;
    const float* Eb = E + (size_t)b * C_ * N_;
    const float* Qb = Q + (size_t)b * C_ * N_;
    float*       Sb = S + (size_t)b * N_ * N_;
    int n0 = blockIdx.y * 128, m0 = blockIdx.x * 128;

    __shared__ float As[8][PITCH], Bs[8][PITCH];
    int t  = threadIdx.x;
    int lk = t >> 5, lc = (t & 31) << 2;        // loader: k-row, 4-col
    int tr = (t >> 4) << 3, tc = (t & 15) << 3; // compute coords
    ZERO_ACC(acc);

    for (int c0 = 0; c0 < C_; c0 += 8) {
        *(float4*)&As[lk][lc] = *(const float4*)(Eb + (size_t)(c0 + lk) * N_ + n0 + lc);
        *(float4*)&Bs[lk][lc] = *(const float4*)(Qb + (size_t)(c0 + lk) * N_ + m0 + lc);
        __syncthreads();
        mac_step(As, Bs, tr, tc, acc);
        __syncthreads();
    }
#pragma unroll
    for (int i = 0; i < 8; ++i) {
        float* dst = Sb + (size_t)(n0 + tr + i) * N_ + m0 + tc;
        *(float4*)(dst)     = make_float4(acc[i][0], acc[i][1], acc[i][2], acc[i][3]);
        *(float4*)(dst + 4) = make_float4(acc[i][4], acc[i][5], acc[i][6], acc[i][7]);
    }
}

// ---------------------------------------------------------------------------
// Row softmax over m (row length 1024). grid = B_*N_, 256 threads (4 elems each)
// ---------------------------------------------------------------------------
__global__ void __launch_bounds__(256) k_softmax(float* __restrict__ S) {
    float* row = S + (size_t)blockIdx.x * N_;
    int t = threadIdx.x;
    float4 v = *(float4*)(row + 4 * t);
    __shared__ float red[8];

    float m = fmaxf(fmaxf(v.x, v.y), fmaxf(v.z, v.w));
#pragma unroll
    for (int o = 16; o; o >>= 1) m = fmaxf(m, __shfl_xor_sync(0xffffffffu, m, o));
    if ((t & 31) == 0) red[t >> 5] = m;
    __syncthreads();
    float mx = red[0];
#pragma unroll
    for (int i = 1; i < 8; ++i) mx = fmaxf(mx, red[i]);
    __syncthreads();

    v.x = __expf(v.x - mx); v.y = __expf(v.y - mx);
    v.z = __expf(v.z - mx); v.w = __expf(v.w - mx);
    float s = v.x + v.y + v.z + v.w;
#pragma unroll
    for (int o = 16; o; o >>= 1) s += __shfl_xor_sync(0xffffffffu, s, o);
    if ((t & 31) == 0) red[t >> 5] = s;
    __syncthreads();
    float tot = red[0];
#pragma unroll
    for (int i = 1; i < 8; ++i) tot += red[i];
    float inv = 1.f / tot;
    v.x *= inv; v.y *= inv; v.z *= inv; v.w *= inv;
    *(float4*)(row + 4 * t) = v;
}

// ---------------------------------------------------------------------------
// Attention output: O[b,c,n] = sum_m Q[b,c,m] * S[b,n,m]   (NT GEMM, K=1024)
// grid (8, 4, 16)
// ---------------------------------------------------------------------------
__global__ void __launch_bounds__(256) k_attmm(const float* __restrict__ Q,
                                               const float* __restrict__ S,
                                               float* __restrict__ O) {
    int b = blockIdx.z;
    const float* Qb = Q + (size_t)b * C_ * N_;
    const float* Sb = S + (size_t)b * N_ * N_;
    float*       Ob = O + (size_t)b * C_ * N_;
    int c0 = blockIdx.y * 128, n0 = blockIdx.x * 128;

    __shared__ float As[8][PITCH], Bs[8][PITCH];
    int t  = threadIdx.x;
    int lr = t >> 1, ls = (t & 1) << 2;         // loader: tile row, k-segment
    int tr = (t >> 4) << 3, tc = (t & 15) << 3;
    ZERO_ACC(acc);

    for (int m0 = 0; m0 < N_; m0 += 8) {
        float4 a = *(const float4*)(Qb + (size_t)(c0 + lr) * N_ + m0 + ls);
        float4 bv = *(const float4*)(Sb + (size_t)(n0 + lr) * N_ + m0 + ls);
        As[ls + 0][lr] = a.x;  As[ls + 1][lr] = a.y;  As[ls + 2][lr] = a.z;  As[ls + 3][lr] = a.w;
        Bs[ls + 0][lr] = bv.x; Bs[ls + 1][lr] = bv.y; Bs[ls + 2][lr] = bv.z; Bs[ls + 3][lr] = bv.w;
        __syncthreads();
        mac_step(As, Bs, tr, tc, acc);
        __syncthreads();
    }
#pragma unroll
    for (int i = 0; i < 8; ++i) {
        float* dst = Ob + (size_t)(c0 + tr + i) * N_ + n0 + tc;
        *(float4*)(dst)     = make_float4(acc[i][0], acc[i][1], acc[i][2], acc[i][3]);
        *(float4*)(dst + 4) = make_float4(acc[i][4], acc[i][5], acc[i][6], acc[i][7]);
    }
}

// ---------------------------------------------------------------------------
// 1x1 conv GEMM with concatenated B operand [X0; X1] (1024 channels), K=1024
// Y[b,co,p] = act( sum_ci W[co,ci] * Xcat[b,ci,p] + bias[co] )
// act: 0 none, 1 sigmoid, 2 tanh.  grid (8, 4, 16)
// ---------------------------------------------------------------------------
__global__ void __launch_bounds__(256) k_gemm1x1(const float* __restrict__ W,
                                                 const float* __restrict__ X0,
                                                 const float* __restrict__ X1,
                                                 const float* __restrict__ bias,
                                                 float* __restrict__ Y, int act) {
    int b = blockIdx.z;
    const float* x0 = X0 + (size_t)b * C_ * N_;
    const float* x1 = X1 + (size_t)b * C_ * N_;
    float*       Yb = Y  + (size_t)b * C_ * N_;
    int co0 = blockIdx.y * 128, p0 = blockIdx.x * 128;

    __shared__ float As[8][PITCH], Bs[8][PITCH];
    int t  = threadIdx.x;
    int lr = t >> 1, ls = (t & 1) << 2;     // A loader (transpose to smem)
    int lk = t >> 5, lp = (t & 31) << 2;    // B loader (direct)
    int tr = (t >> 4) << 3, tc = (t & 15) << 3;
    ZERO_ACC(acc);

    for (int k0 = 0; k0 < 2 * C_; k0 += 8) {
        float4 a = *(const float4*)(W + (size_t)(co0 + lr) * (2 * C_) + k0 + ls);
        As[ls + 0][lr] = a.x; As[ls + 1][lr] = a.y; As[ls + 2][lr] = a.z; As[ls + 3][lr] = a.w;
        int ci = k0 + lk;
        const float* src = (ci < C_) ? (x0 + (size_t)ci * N_) : (x1 + (size_t)(ci - C_) * N_);
        *(float4*)&Bs[lk][lp] = *(const float4*)(src + p0 + lp);
        __syncthreads();
        mac_step(As, Bs, tr, tc, acc);
        __syncthreads();
    }
#pragma unroll
    for (int i = 0; i < 8; ++i) {
        float bv = bias[co0 + tr + i];
        float o[8];
#pragma unroll
        for (int j = 0; j < 8; ++j) {
            float v = acc[i][j] + bv;
            if (act == 1)      v = 1.f / (1.f + __expf(-v));
            else if (act == 2) v = tanhf(v);
            o[j] = v;
        }
        float* dst = Yb + (size_t)(co0 + tr + i) * N_ + p0 + tc;
        *(float4*)(dst)     = make_float4(o[0], o[1], o[2], o[3]);
        *(float4*)(dst + 4) = make_float4(o[4], o[5], o[6], o[7]);
    }
}

// ---------------------------------------------------------------------------
// 3x3 conv, pad 1, as implicit GEMM over K = 9*1024, concat B operand.
// Wt layout: [tap][co][ci] (pre-transposed).  grid (8, 4, 16)
// ---------------------------------------------------------------------------
__global__ void __launch_bounds__(256) k_conv3(const float* __restrict__ Wt,
                                               const float* __restrict__ X0,
                                               const float* __restrict__ X1,
                                               const float* __restrict__ bias,
                                               float* __restrict__ Y) {
    int b = blockIdx.z;
    const float* x0 = X0 + (size_t)b * C_ * N_;
    const float* x1 = X1 + (size_t)b * C_ * N_;
    float*       Yb = Y  + (size_t)b * C_ * N_;
    int co0 = blockIdx.y * 128, p0 = blockIdx.x * 128;

    __shared__ float As[8][PITCH], Bs[8][PITCH];
    int t  = threadIdx.x;
    int lr = t >> 1, ls = (t & 1) << 2;
    int lk = t >> 5, lp = (t & 31) << 2;
    int tr = (t >> 4) << 3, tc = (t & 15) << 3;
    ZERO_ACC(acc);

    for (int tap = 0; tap < 9; ++tap) {
        int dy = tap / 3 - 1, dx = tap % 3 - 1;
        const float* Wtap = Wt + (size_t)tap * C_ * (2 * C_);
        for (int k0 = 0; k0 < 2 * C_; k0 += 8) {
            float4 a = *(const float4*)(Wtap + (size_t)(co0 + lr) * (2 * C_) + k0 + ls);
            As[ls + 0][lr] = a.x; As[ls + 1][lr] = a.y; As[ls + 2][lr] = a.z; As[ls + 3][lr] = a.w;
            int ci = k0 + lk;
            const float* src = (ci < C_) ? (x0 + (size_t)ci * N_) : (x1 + (size_t)(ci - C_) * N_);
#pragma unroll
            for (int j = 0; j < 4; ++j) {
                int p = p0 + lp + j;
                int y = (p >> 5) + dy;
                int x = (p & 31) + dx;
                float v = 0.f;
                if ((unsigned)y < HW && (unsigned)x < HW) v = src[y * HW + x];
                Bs[lk][lp + j] = v;
            }
            __syncthreads();
            mac_step(As, Bs, tr, tc, acc);
            __syncthreads();
        }
    }
#pragma unroll
    for (int i = 0; i < 8; ++i) {
        float bv = bias[co0 + tr + i];
        float* dst = Yb + (size_t)(co0 + tr + i) * N_ + p0 + tc;
        *(float4*)(dst)     = make_float4(acc[i][0] + bv, acc[i][1] + bv, acc[i][2] + bv, acc[i][3] + bv);
        *(float4*)(dst + 4) = make_float4(acc[i][4] + bv, acc[i][5] + bv, acc[i][6] + bv, acc[i][7] + bv);
    }
}

// ---------------------------------------------------------------------------
// Small utility kernels
// ---------------------------------------------------------------------------
__global__ void k_wt(const float* __restrict__ w, float* __restrict__ wt) {
    size_t i = (size_t)blockIdx.x * 256 + threadIdx.x;
    if (i >= WTSZ) return;
    int ci  = (int)(i % (2 * C_));
    int co  = (int)((i / (2 * C_)) % C_);
    int tap = (int)(i / ((size_t)C_ * 2 * C_));
    wt[i] = w[((size_t)co * (2 * C_) + ci) * 9 + tap];
}

__global__ void k_init(const float* __restrict__ a, const float* __restrict__ b,
                       const float* __restrict__ c) {
    size_t i = ((size_t)blockIdx.x * 256 + threadIdx.x) * 4;
    *(float4*)(g_ex + i) = *(const float4*)(a + i);
    *(float4*)(g_q  + i) = *(const float4*)(b + i);
    *(float4*)(g_q1 + i) = *(const float4*)(c + i);
}

__global__ void k_mul(float* __restrict__ r, const float* __restrict__ h) {
    size_t i = ((size_t)blockIdx.x * 256 + threadIdx.x) * 4;
    float4 a = *(float4*)(r + i);
    float4 b = *(const float4*)(h + i);
    a.x *= b.x; a.y *= b.y; a.z *= b.z; a.w *= b.w;
    *(float4*)(r + i) = a;
}

__global__ void k_gruout(float* __restrict__ h, const float* __restrict__ u,
                         const float* __restrict__ c) {
    size_t i = ((size_t)blockIdx.x * 256 + threadIdx.x) * 4;
    float4 hv = *(float4*)(h + i);
    float4 uv = *(const float4*)(u + i);
    float4 cv = *(const float4*)(c + i);
    hv.x = hv.x * (1.f - uv.x) + cv.x * uv.x;
    hv.y = hv.y * (1.f - uv.y) + cv.y * uv.y;
    hv.z = hv.z * (1.f - uv.z) + cv.z * uv.z;
    hv.w = hv.w * (1.f - uv.w) + cv.w * uv.w;
    *(float4*)(h + i) = hv;
}

// ---------------------------------------------------------------------------
// Host orchestration
// ---------------------------------------------------------------------------
static void attention(const float* Xe, const float* Xq, float* O, float* Sbuf) {
    k_scores<<<dim3(8, 8, B_), 256>>>(Xe, Xq, Sbuf);
    k_softmax<<<B_ * N_, 256>>>(Sbuf);
    k_attmm<<<dim3(8, 4, B_), 256>>>(Xq, Sbuf, O);
}

extern "C" void kernel_launch(void* const* d_in, const int* in_sizes, int n_in,
                              void* d_out, int out_size) {
    const float* in1      = (const float*)d_in[0];
    const float* in2      = (const float*)d_in[1];
    const float* in3      = (const float*)d_in[2];
    const float* w_fusion = (const float*)d_in[3];
    const float* b_fusion = (const float*)d_in[4];
    const float* w_out    = (const float*)d_in[5];
    const float* b_out    = (const float*)d_in[6];
    const float* w_reset  = (const float*)d_in[7];
    const float* b_reset  = (const float*)d_in[8];
    const float* w_update = (const float*)d_in[9];
    const float* b_update = (const float*)d_in[10];
    const float* w_cand   = (const float*)d_in[11];
    const float* b_cand   = (const float*)d_in[12];
    float* out = (float*)d_out;

    float *S, *O1, *O2, *a1, *a2, *a3, *ex, *q, *q1, *r, *u, *c, *wf, *wo;
    cudaGetSymbolAddress((void**)&S,  g_S);
    cudaGetSymbolAddress((void**)&O1, g_O1);
    cudaGetSymbolAddress((void**)&O2, g_O2);
    cudaGetSymbolAddress((void**)&a1, g_a1);
    cudaGetSymbolAddress((void**)&a2, g_a2);
    cudaGetSymbolAddress((void**)&a3, g_a3);
    cudaGetSymbolAddress((void**)&ex, g_ex);
    cudaGetSymbolAddress((void**)&q,  g_q);
    cudaGetSymbolAddress((void**)&q1, g_q1);
    cudaGetSymbolAddress((void**)&r,  g_r);
    cudaGetSymbolAddress((void**)&u,  g_u);
    cudaGetSymbolAddress((void**)&c,  g_c);
    cudaGetSymbolAddress((void**)&wf, g_wf);
    cudaGetSymbolAddress((void**)&wo, g_wo);

    const int EWG = (int)(TSZ / 4 / 256);            // 8192
    const int WTG = (int)((WTSZ + 255) / 256);       // 18432

    k_init<<<EWG, 256>>>(in1, in2, in3);
    k_wt<<<WTG, 256>>>(w_fusion, wf);
    k_wt<<<WTG, 256>>>(w_out, wo);

    dim3 gA(8, 4, B_);
    for (int round = 0; round < 5; ++round) {
        // all attentions + fusion convs use the PRE-update states
        attention(ex, q,  O1, S);
        attention(ex, q1, O2, S);
        k_conv3<<<gA, 256>>>(wf, O1, O2, b_fusion, a1);

        attention(q, ex, O1, S);
        attention(q, q1, O2, S);
        k_conv3<<<gA, 256>>>(wf, O1, O2, b_fusion, a2);

        attention(q1, ex, O1, S);
        attention(q1, q,  O2, S);
        k_conv3<<<gA, 256>>>(wf, O1, O2, b_fusion, a3);

        // GRU updates (each independent; uses own x,h only)
        float* xs[3] = {a1, a2, a3};
        float* hs[3] = {ex, q, q1};
        for (int s = 0; s < 3; ++s) {
            k_gemm1x1<<<gA, 256>>>(w_reset,  xs[s], hs[s], b_reset,  r, 1);
            k_gemm1x1<<<gA, 256>>>(w_update, xs[s], hs[s], b_update, u, 1);
            k_mul<<<EWG, 256>>>(r, hs[s]);                       // r <- r * h
            k_gemm1x1<<<gA, 256>>>(w_cand, xs[s], r, b_cand, c, 2);
            k_gruout<<<EWG, 256>>>(hs[s], u, c);                 // h <- h(1-u)+cu
        }
    }

    k_conv3<<<gA, 256>>>(wo, ex, in1, b_out, out);
    k_conv3<<<gA, 256>>>(wo, q,  in2, b_out, out + TSZ);
    k_conv3<<<gA, 256>>>(wo, q1, in3, b_out, out + 2 * TSZ);
}

// round 2
// speedup vs baseline: 2.1584x; 2.1584x over previous
#include <cuda_runtime.h>
#include <math.h>
#include <stdint.h>

// ---------------------------------------------------------------------------
// Problem constants
// ---------------------------------------------------------------------------
#define B_  16
#define C_  512
#define N_  1024
#define HW  32
#define PITCH2 136   // smem pitch (floats): 136 mod 32 = 8 -> conflict-free frags

static constexpr size_t TSZ  = (size_t)B_ * C_ * N_;
static constexpr size_t WTSZ = (size_t)9 * C_ * (2 * C_);

// ---------------------------------------------------------------------------
// Scratch (static device globals; no allocation anywhere)
// ---------------------------------------------------------------------------
__device__ float g_S [(size_t)B_ * N_ * N_];
__device__ float g_O1[TSZ], g_O2[TSZ];
__device__ float g_a1[TSZ], g_a2[TSZ], g_a3[TSZ];
__device__ float g_ex[TSZ], g_q [TSZ], g_q1[TSZ];
__device__ float g_r [TSZ], g_u [TSZ], g_c [TSZ];
__device__ float g_wf[WTSZ], g_wo[WTSZ];

// ---------------------------------------------------------------------------
// tf32 mma.sync microkernel pieces
// ---------------------------------------------------------------------------
__device__ __forceinline__ uint32_t f2tf(float f) {
    uint32_t u;
    asm("cvt.rna.tf32.f32 %0, %1;" : "=r"(u) : "f"(f));
    return u;
}

__device__ __forceinline__ void mma8(float* d, const uint32_t* a, const uint32_t* b) {
    asm volatile(
        "mma.sync.aligned.m16n8k8.row.col.f32.tf32.tf32.f32 "
        "{%0,%1,%2,%3}, {%4,%5,%6,%7}, {%8,%9}, {%0,%1,%2,%3};\n"
        : "+f"(d[0]), "+f"(d[1]), "+f"(d[2]), "+f"(d[3])
        : "r"(a[0]), "r"(a[1]), "r"(a[2]), "r"(a[3]), "r"(b[0]), "r"(b[1]));
}

// Compute one BK=16 slab: warp tile 64x32 (4 m-tiles x 4 n-tiles of m16n8k8)
__device__ __forceinline__ void compute_bk16(const float (*As)[PITCH2],
                                             const float (*Bs)[PITCH2],
                                             float acc[4][4][4],
                                             int wm, int wn, int lane) {
    int g = lane >> 2, tg = lane & 3;
#pragma unroll
    for (int ks = 0; ks < 2; ++ks) {
        int k0 = ks * 8;
        uint32_t a[4][4], b[4][2];
#pragma unroll
        for (int mt = 0; mt < 4; ++mt) {
            int m = wm + mt * 16 + g;
            a[mt][0] = f2tf(As[k0 + tg    ][m    ]);
            a[mt][1] = f2tf(As[k0 + tg    ][m + 8]);
            a[mt][2] = f2tf(As[k0 + tg + 4][m    ]);
            a[mt][3] = f2tf(As[k0 + tg + 4][m + 8]);
        }
#pragma unroll
        for (int nt = 0; nt < 4; ++nt) {
            int n = wn + nt * 8 + g;
            b[nt][0] = f2tf(Bs[k0 + tg    ][n]);
            b[nt][1] = f2tf(Bs[k0 + tg + 4][n]);
        }
#pragma unroll
        for (int mt = 0; mt < 4; ++mt)
#pragma unroll
            for (int nt = 0; nt < 4; ++nt)
                mma8(acc[mt][nt], a[mt], b[nt]);
    }
}

#define ZERO_ACC(acc)                                       \
    float acc[4][4][4];                                     \
    _Pragma("unroll")                                       \
    for (int i_ = 0; i_ < 4; ++i_)                          \
        _Pragma("unroll")                                   \
        for (int j_ = 0; j_ < 4; ++j_)                      \
            _Pragma("unroll")                               \
            for (int v_ = 0; v_ < 4; ++v_) acc[i_][j_][v_] = 0.f;

// ---------------------------------------------------------------------------
// k_scores: S[b,n,m] = sum_c E[b,c,n] * Q[b,c,m]   (both operands k-major rows)
// grid (8, 8, 16), 256 threads
// ---------------------------------------------------------------------------
__global__ void __launch_bounds__(256) k_scores(const float* __restrict__ E,
                                                const float* __restrict__ Q,
                                                float* __restrict__ S) {
    int b = blockIdx.z;
    const float* Eb = E + (size_t)b * C_ * N_;
    const float* Qb = Q + (size_t)b * C_ * N_;
    float*       Sb = S + (size_t)b * N_ * N_;
    int n0 = blockIdx.y * 128, m0 = blockIdx.x * 128;

    __shared__ float As[2][16][PITCH2], Bs[2][16][PITCH2];
    int t = threadIdx.x, lane = t & 31, wid = t >> 5;
    int wm = (wid & 1) * 64, wn = (wid >> 1) * 32;
    int lrow = t >> 5, lcol = (t & 31) * 4;    // direct loader: 8 rows x 128 cols, x2

    float4 pa[2], pb[2];
#pragma unroll
    for (int i = 0; i < 2; ++i) {
        pa[i] = *(const float4*)(Eb + (size_t)(lrow + i * 8) * N_ + n0 + lcol);
        pb[i] = *(const float4*)(Qb + (size_t)(lrow + i * 8) * N_ + m0 + lcol);
        *(float4*)&As[0][lrow + i * 8][lcol] = pa[i];
        *(float4*)&Bs[0][lrow + i * 8][lcol] = pb[i];
    }
    __syncthreads();

    ZERO_ACC(acc);
    const int KI = C_ / 16;
    for (int it = 0; it < KI; ++it) {
        int nx = it + 1;
        if (nx < KI) {
#pragma unroll
            for (int i = 0; i < 2; ++i) {
                pa[i] = *(const float4*)(Eb + (size_t)(nx * 16 + lrow + i * 8) * N_ + n0 + lcol);
                pb[i] = *(const float4*)(Qb + (size_t)(nx * 16 + lrow + i * 8) * N_ + m0 + lcol);
            }
        }
        compute_bk16(As[it & 1], Bs[it & 1], acc, wm, wn, lane);
        if (nx < KI) {
#pragma unroll
            for (int i = 0; i < 2; ++i) {
                *(float4*)&As[nx & 1][lrow + i * 8][lcol] = pa[i];
                *(float4*)&Bs[nx & 1][lrow + i * 8][lcol] = pb[i];
            }
        }
        __syncthreads();
    }

    int g = lane >> 2, tg = lane & 3;
#pragma unroll
    for (int mt = 0; mt < 4; ++mt)
#pragma unroll
        for (int nt = 0; nt < 4; ++nt) {
            int row = n0 + wm + mt * 16 + g;
            int col = m0 + wn + nt * 8 + tg * 2;
            *(float2*)(Sb + (size_t)row * N_ + col)       = make_float2(acc[mt][nt][0], acc[mt][nt][1]);
            *(float2*)(Sb + (size_t)(row + 8) * N_ + col) = make_float2(acc[mt][nt][2], acc[mt][nt][3]);
        }
}

// ---------------------------------------------------------------------------
// Row softmax over m (row length 1024). grid = B_*N_, 256 threads
// ---------------------------------------------------------------------------
__global__ void __launch_bounds__(256) k_softmax(float* __restrict__ S) {
    float* row = S + (size_t)blockIdx.x * N_;
    int t = threadIdx.x;
    float4 v = *(float4*)(row + 4 * t);
    __shared__ float red[8];

    float m = fmaxf(fmaxf(v.x, v.y), fmaxf(v.z, v.w));
#pragma unroll
    for (int o = 16; o; o >>= 1) m = fmaxf(m, __shfl_xor_sync(0xffffffffu, m, o));
    if ((t & 31) == 0) red[t >> 5] = m;
    __syncthreads();
    float mx = red[0];
#pragma unroll
    for (int i = 1; i < 8; ++i) mx = fmaxf(mx, red[i]);
    __syncthreads();

    v.x = __expf(v.x - mx); v.y = __expf(v.y - mx);
    v.z = __expf(v.z - mx); v.w = __expf(v.w - mx);
    float s = v.x + v.y + v.z + v.w;
#pragma unroll
    for (int o = 16; o; o >>= 1) s += __shfl_xor_sync(0xffffffffu, s, o);
    if ((t & 31) == 0) red[t >> 5] = s;
    __syncthreads();
    float tot = red[0];
#pragma unroll
    for (int i = 1; i < 8; ++i) tot += red[i];
    float inv = 1.f / tot;
    v.x *= inv; v.y *= inv; v.z *= inv; v.w *= inv;
    *(float4*)(row + 4 * t) = v;
}

// ---------------------------------------------------------------------------
// k_attmm: O[b,c,n] = sum_m Q[b,c,m] * S[b,n,m]   (both transposed to smem)
// grid (8, 4, 16)
// ---------------------------------------------------------------------------
__global__ void __launch_bounds__(256) k_attmm(const float* __restrict__ Q,
                                               const float* __restrict__ S,
                                               float* __restrict__ O) {
    int b = blockIdx.z;
    const float* Qb = Q + (size_t)b * C_ * N_;
    const float* Sb = S + (size_t)b * N_ * N_;
    float*       Ob = O + (size_t)b * C_ * N_;
    int c0 = blockIdx.y * 128, n0 = blockIdx.x * 128;

    __shared__ float As[2][16][PITCH2], Bs[2][16][PITCH2];
    int t = threadIdx.x, lane = t & 31, wid = t >> 5;
    int wm = (wid & 1) * 64, wn = (wid >> 1) * 32;
    int lr = t & 127, ls = (t >> 7) * 8;       // transposing loader

    float4 pa[2], pb[2];
    pa[0] = *(const float4*)(Qb + (size_t)(c0 + lr) * N_ + ls);
    pa[1] = *(const float4*)(Qb + (size_t)(c0 + lr) * N_ + ls + 4);
    pb[0] = *(const float4*)(Sb + (size_t)(n0 + lr) * N_ + ls);
    pb[1] = *(const float4*)(Sb + (size_t)(n0 + lr) * N_ + ls + 4);
#pragma unroll
    for (int j = 0; j < 4; ++j) {
        As[0][ls + j][lr] = (&pa[0].x)[j];  As[0][ls + 4 + j][lr] = (&pa[1].x)[j];
        Bs[0][ls + j][lr] = (&pb[0].x)[j];  Bs[0][ls + 4 + j][lr] = (&pb[1].x)[j];
    }
    __syncthreads();

    ZERO_ACC(acc);
    const int KI = N_ / 16;
    for (int it = 0; it < KI; ++it) {
        int nx = it + 1;
        if (nx < KI) {
            int k0 = nx * 16 + ls;
            pa[0] = *(const float4*)(Qb + (size_t)(c0 + lr) * N_ + k0);
            pa[1] = *(const float4*)(Qb + (size_t)(c0 + lr) * N_ + k0 + 4);
            pb[0] = *(const float4*)(Sb + (size_t)(n0 + lr) * N_ + k0);
            pb[1] = *(const float4*)(Sb + (size_t)(n0 + lr) * N_ + k0 + 4);
        }
        compute_bk16(As[it & 1], Bs[it & 1], acc, wm, wn, lane);
        if (nx < KI) {
            int sb = nx & 1;
#pragma unroll
            for (int j = 0; j < 4; ++j) {
                As[sb][ls + j][lr] = (&pa[0].x)[j];  As[sb][ls + 4 + j][lr] = (&pa[1].x)[j];
                Bs[sb][ls + j][lr] = (&pb[0].x)[j];  Bs[sb][ls + 4 + j][lr] = (&pb[1].x)[j];
            }
        }
        __syncthreads();
    }

    int g = lane >> 2, tg = lane & 3;
#pragma unroll
    for (int mt = 0; mt < 4; ++mt)
#pragma unroll
        for (int nt = 0; nt < 4; ++nt) {
            int row = c0 + wm + mt * 16 + g;
            int col = n0 + wn + nt * 8 + tg * 2;
            *(float2*)(Ob + (size_t)row * N_ + col)       = make_float2(acc[mt][nt][0], acc[mt][nt][1]);
            *(float2*)(Ob + (size_t)(row + 8) * N_ + col) = make_float2(acc[mt][nt][2], acc[mt][nt][3]);
        }
}

// ---------------------------------------------------------------------------
// k_gemm1x1: Y[b,co,p] = act( sum_ci W[co,ci] * Xcat[b,ci,p] + bias[co] )
// A transposed to smem, B direct with two-pointer concat. grid (8, 4, 16)
// ---------------------------------------------------------------------------
__global__ void __launch_bounds__(256) k_gemm1x1(const float* __restrict__ W,
                                                 const float* __restrict__ X0,
                                                 const float* __restrict__ X1,
                                                 const float* __restrict__ bias,
                                                 float* __restrict__ Y, int act) {
    int b = blockIdx.z;
    const float* x0 = X0 + (size_t)b * C_ * N_;
    const float* x1 = X1 + (size_t)b * C_ * N_;
    float*       Yb = Y  + (size_t)b * C_ * N_;
    int co0 = blockIdx.y * 128, p0 = blockIdx.x * 128;

    __shared__ float As[2][16][PITCH2], Bs[2][16][PITCH2];
    int t = threadIdx.x, lane = t & 31, wid = t >> 5;
    int wm = (wid & 1) * 64, wn = (wid >> 1) * 32;
    int lr = t & 127, ls = (t >> 7) * 8;       // A transposing loader
    int brow = t >> 5, bcol = (t & 31) * 4;    // B direct loader

    float4 pa[2], pb[2];
    {
        pa[0] = *(const float4*)(W + (size_t)(co0 + lr) * (2 * C_) + ls);
        pa[1] = *(const float4*)(W + (size_t)(co0 + lr) * (2 * C_) + ls + 4);
#pragma unroll
        for (int i = 0; i < 2; ++i) {
            int ci = brow + i * 8;
            const float* src = (ci < C_) ? (x0 + (size_t)ci * N_) : (x1 + (size_t)(ci - C_) * N_);
            pb[i] = *(const float4*)(src + p0 + bcol);
        }
#pragma unroll
        for (int j = 0; j < 4; ++j) {
            As[0][ls + j][lr] = (&pa[0].x)[j];  As[0][ls + 4 + j][lr] = (&pa[1].x)[j];
        }
        *(float4*)&Bs[0][brow][bcol]     = pb[0];
        *(float4*)&Bs[0][brow + 8][bcol] = pb[1];
    }
    __syncthreads();

    ZERO_ACC(acc);
    const int KI = (2 * C_) / 16;
    for (int it = 0; it < KI; ++it) {
        int nx = it + 1;
        if (nx < KI) {
            int k0 = nx * 16;
            pa[0] = *(const float4*)(W + (size_t)(co0 + lr) * (2 * C_) + k0 + ls);
            pa[1] = *(const float4*)(W + (size_t)(co0 + lr) * (2 * C_) + k0 + ls + 4);
#pragma unroll
            for (int i = 0; i < 2; ++i) {
                int ci = k0 + brow + i * 8;
                const float* src = (ci < C_) ? (x0 + (size_t)ci * N_) : (x1 + (size_t)(ci - C_) * N_);
                pb[i] = *(const float4*)(src + p0 + bcol);
            }
        }
        compute_bk16(As[it & 1], Bs[it & 1], acc, wm, wn, lane);
        if (nx < KI) {
            int sb = nx & 1;
#pragma unroll
            for (int j = 0; j < 4; ++j) {
                As[sb][ls + j][lr] = (&pa[0].x)[j];  As[sb][ls + 4 + j][lr] = (&pa[1].x)[j];
            }
            *(float4*)&Bs[sb][brow][bcol]     = pb[0];
            *(float4*)&Bs[sb][brow + 8][bcol] = pb[1];
        }
        __syncthreads();
    }

    int g = lane >> 2, tg = lane & 3;
#pragma unroll
    for (int mt = 0; mt < 4; ++mt) {
#pragma unroll
        for (int nt = 0; nt < 4; ++nt) {
            int row = co0 + wm + mt * 16 + g;
            int col = p0 + wn + nt * 8 + tg * 2;
            float bv0 = bias[row], bv1 = bias[row + 8];
            float o[4] = {acc[mt][nt][0] + bv0, acc[mt][nt][1] + bv0,
                          acc[mt][nt][2] + bv1, acc[mt][nt][3] + bv1};
#pragma unroll
            for (int v = 0; v < 4; ++v) {
                if (act == 1)      o[v] = 1.f / (1.f + __expf(-o[v]));
                else if (act == 2) o[v] = tanhf(o[v]);
            }
            *(float2*)(Yb + (size_t)row * N_ + col)       = make_float2(o[0], o[1]);
            *(float2*)(Yb + (size_t)(row + 8) * N_ + col) = make_float2(o[2], o[3]);
        }
    }
}

// ---------------------------------------------------------------------------
// k_conv3: 3x3 conv pad 1, implicit GEMM over K = 9*1024, concat B operand.
// Wt layout: [tap][co][ci].  grid (8, 4, 16)
// ---------------------------------------------------------------------------
__global__ void __launch_bounds__(256) k_conv3(const float* __restrict__ Wt,
                                               const float* __restrict__ X0,
                                               const float* __restrict__ X1,
                                               const float* __restrict__ bias,
                                               float* __restrict__ Y) {
    int b = blockIdx.z;
    const float* x0 = X0 + (size_t)b * C_ * N_;
    const float* x1 = X1 + (size_t)b * C_ * N_;
    float*       Yb = Y  + (size_t)b * C_ * N_;
    int co0 = blockIdx.y * 128, p0 = blockIdx.x * 128;

    __shared__ float As[2][16][PITCH2], Bs[2][16][PITCH2];
    int t = threadIdx.x, lane = t & 31, wid = t >> 5;
    int wm = (wid & 1) * 64, wn = (wid >> 1) * 32;
    int lr = t & 127, ls = (t >> 7) * 8;
    int brow = t >> 5, bcol = (t & 31) * 4;

    float4 pa[2], pb[2];

    auto loadA = [&](int it, float4* pav) {
        int tap = it >> 6, k0 = (it & 63) * 16;
        const float* wrow = Wt + (size_t)tap * C_ * (2 * C_) + (size_t)(co0 + lr) * (2 * C_) + k0 + ls;
        pav[0] = *(const float4*)(wrow);
        pav[1] = *(const float4*)(wrow + 4);
    };
    auto loadB = [&](int it, float4* pbv) {
        int tap = it >> 6, k0 = (it & 63) * 16;
        int dy = tap / 3 - 1, dx = tap % 3 - 1;
#pragma unroll
        for (int i = 0; i < 2; ++i) {
            int ci = k0 + brow + i * 8;
            const float* src = (ci < C_) ? (x0 + (size_t)ci * N_) : (x1 + (size_t)(ci - C_) * N_);
            float v[4];
#pragma unroll
            for (int j = 0; j < 4; ++j) {
                int p = p0 + bcol + j;
                int y = (p >> 5) + dy;
                int x = (p & 31) + dx;
                v[j] = ((unsigned)y < HW && (unsigned)x < HW) ? src[y * HW + x] : 0.f;
            }
            pbv[i] = make_float4(v[0], v[1], v[2], v[3]);
        }
    };
    auto stage = [&](int sb, const float4* pav, const float4* pbv) {
#pragma unroll
        for (int j = 0; j < 4; ++j) {
            As[sb][ls + j][lr] = (&pav[0].x)[j];  As[sb][ls + 4 + j][lr] = (&pav[1].x)[j];
        }
        *(float4*)&Bs[sb][brow][bcol]     = pbv[0];
        *(float4*)&Bs[sb][brow + 8][bcol] = pbv[1];
    };

    loadA(0, pa); loadB(0, pb); stage(0, pa, pb);
    __syncthreads();

    ZERO_ACC(acc);
    const int KI = 9 * (2 * C_) / 16;   // 576
    for (int it = 0; it < KI; ++it) {
        int nx = it + 1;
        if (nx < KI) { loadA(nx, pa); loadB(nx, pb); }
        compute_bk16(As[it & 1], Bs[it & 1], acc, wm, wn, lane);
        if (nx < KI) stage(nx & 1, pa, pb);
        __syncthreads();
    }

    int g = lane >> 2, tg = lane & 3;
#pragma unroll
    for (int mt = 0; mt < 4; ++mt)
#pragma unroll
        for (int nt = 0; nt < 4; ++nt) {
            int row = co0 + wm + mt * 16 + g;
            int col = p0 + wn + nt * 8 + tg * 2;
            float bv0 = bias[row], bv1 = bias[row + 8];
            *(float2*)(Yb + (size_t)row * N_ + col)       = make_float2(acc[mt][nt][0] + bv0, acc[mt][nt][1] + bv0);
            *(float2*)(Yb + (size_t)(row + 8) * N_ + col) = make_float2(acc[mt][nt][2] + bv1, acc[mt][nt][3] + bv1);
        }
}

// ---------------------------------------------------------------------------
// Small utility kernels
// ---------------------------------------------------------------------------
__global__ void k_wt(const float* __restrict__ w, float* __restrict__ wt) {
    size_t i = (size_t)blockIdx.x * 256 + threadIdx.x;
    if (i >= WTSZ) return;
    int ci  = (int)(i % (2 * C_));
    int co  = (int)((i / (2 * C_)) % C_);
    int tap = (int)(i / ((size_t)C_ * 2 * C_));
    wt[i] = w[((size_t)co * (2 * C_) + ci) * 9 + tap];
}

__global__ void k_init(const float* __restrict__ a, const float* __restrict__ b,
                       const float* __restrict__ c) {
    size_t i = ((size_t)blockIdx.x * 256 + threadIdx.x) * 4;
    *(float4*)(g_ex + i) = *(const float4*)(a + i);
    *(float4*)(g_q  + i) = *(const float4*)(b + i);
    *(float4*)(g_q1 + i) = *(const float4*)(c + i);
}

__global__ void k_mul(float* __restrict__ r, const float* __restrict__ h) {
    size_t i = ((size_t)blockIdx.x * 256 + threadIdx.x) * 4;
    float4 a = *(float4*)(r + i);
    float4 b = *(const float4*)(h + i);
    a.x *= b.x; a.y *= b.y; a.z *= b.z; a.w *= b.w;
    *(float4*)(r + i) = a;
}

__global__ void k_gruout(float* __restrict__ h, const float* __restrict__ u,
                         const float* __restrict__ c) {
    size_t i = ((size_t)blockIdx.x * 256 + threadIdx.x) * 4;
    float4 hv = *(float4*)(h + i);
    float4 uv = *(const float4*)(u + i);
    float4 cv = *(const float4*)(c + i);
    hv.x = hv.x * (1.f - uv.x) + cv.x * uv.x;
    hv.y = hv.y * (1.f - uv.y) + cv.y * uv.y;
    hv.z = hv.z * (1.f - uv.z) + cv.z * uv.z;
    hv.w = hv.w * (1.f - uv.w) + cv.w * uv.w;
    *(float4*)(h + i) = hv;
}

// ---------------------------------------------------------------------------
// Host orchestration
// ---------------------------------------------------------------------------
static void attention(const float* Xe, const float* Xq, float* O, float* Sbuf) {
    k_scores<<<dim3(8, 8, B_), 256>>>(Xe, Xq, Sbuf);
    k_softmax<<<B_ * N_, 256>>>(Sbuf);
    k_attmm<<<dim3(8, 4, B_), 256>>>(Xq, Sbuf, O);
}

extern "C" void kernel_launch(void* const* d_in, const int* in_sizes, int n_in,
                              void* d_out, int out_size) {
    const float* in1      = (const float*)d_in[0];
    const float* in2      = (const float*)d_in[1];
    const float* in3      = (const float*)d_in[2];
    const float* w_fusion = (const float*)d_in[3];
    const float* b_fusion = (const float*)d_in[4];
    const float* w_out    = (const float*)d_in[5];
    const float* b_out    = (const float*)d_in[6];
    const float* w_reset  = (const float*)d_in[7];
    const float* b_reset  = (const float*)d_in[8];
    const float* w_update = (const float*)d_in[9];
    const float* b_update = (const float*)d_in[10];
    const float* w_cand   = (const float*)d_in[11];
    const float* b_cand   = (const float*)d_in[12];
    float* out = (float*)d_out;

    float *S, *O1, *O2, *a1, *a2, *a3, *ex, *q, *q1, *r, *u, *c, *wf, *wo;
    cudaGetSymbolAddress((void**)&S,  g_S);
    cudaGetSymbolAddress((void**)&O1, g_O1);
    cudaGetSymbolAddress((void**)&O2, g_O2);
    cudaGetSymbolAddress((void**)&a1, g_a1);
    cudaGetSymbolAddress((void**)&a2, g_a2);
    cudaGetSymbolAddress((void**)&a3, g_a3);
    cudaGetSymbolAddress((void**)&ex, g_ex);
    cudaGetSymbolAddress((void**)&q,  g_q);
    cudaGetSymbolAddress((void**)&q1, g_q1);
    cudaGetSymbolAddress((void**)&r,  g_r);
    cudaGetSymbolAddress((void**)&u,  g_u);
    cudaGetSymbolAddress((void**)&c,  g_c);
    cudaGetSymbolAddress((void**)&wf, g_wf);
    cudaGetSymbolAddress((void**)&wo, g_wo);

    const int EWG = (int)(TSZ / 4 / 256);
    const int WTG = (int)((WTSZ + 255) / 256);

    k_init<<<EWG, 256>>>(in1, in2, in3);
    k_wt<<<WTG, 256>>>(w_fusion, wf);
    k_wt<<<WTG, 256>>>(w_out, wo);

    dim3 gA(8, 4, B_);
    for (int round = 0; round < 5; ++round) {
        attention(ex, q,  O1, S);
        attention(ex, q1, O2, S);
        k_conv3<<<gA, 256>>>(wf, O1, O2, b_fusion, a1);

        attention(q, ex, O1, S);
        attention(q, q1, O2, S);
        k_conv3<<<gA, 256>>>(wf, O1, O2, b_fusion, a2);

        attention(q1, ex, O1, S);
        attention(q1, q,  O2, S);
        k_conv3<<<gA, 256>>>(wf, O1, O2, b_fusion, a3);

        float* xs[3] = {a1, a2, a3};
        float* hs[3] = {ex, q, q1};
        for (int s = 0; s < 3; ++s) {
            k_gemm1x1<<<gA, 256>>>(w_reset,  xs[s], hs[s], b_reset,  r, 1);
            k_gemm1x1<<<gA, 256>>>(w_update, xs[s], hs[s], b_update, u, 1);
            k_mul<<<EWG, 256>>>(r, hs[s]);
            k_gemm1x1<<<gA, 256>>>(w_cand, xs[s], r, b_cand, c, 2);
            k_gruout<<<EWG, 256>>>(hs[s], u, c);
        }
    }

    k_conv3<<<gA, 256>>>(wo, ex, in1, b_out, out);
    k_conv3<<<gA, 256>>>(wo, q,  in2, b_out, out + TSZ);
    k_conv3<<<gA, 256>>>(wo, q1, in3, b_out, out + 2 * TSZ);
}

// round 3
// speedup vs baseline: 2.5407x; 1.1771x over previous
#include <cuda_runtime.h>
#include <math.h>
#include <stdint.h>

// ---------------------------------------------------------------------------
// Problem constants
// ---------------------------------------------------------------------------
#define B_  16
#define C_  512
#define N_  1024
#define HW  32
#define PITCH2 136   // smem pitch (u32): 136 mod 32 = 8 -> conflict-free frags

static constexpr size_t TSZ  = (size_t)B_ * C_ * N_;
static constexpr size_t WTSZ = (size_t)9 * C_ * (2 * C_);

// ---------------------------------------------------------------------------
// Scratch (static device globals; no allocation anywhere)
// ---------------------------------------------------------------------------
__device__ float g_S [(size_t)B_ * N_ * N_];
__device__ float g_O1[TSZ], g_O2[TSZ];
__device__ float g_a1[TSZ], g_a2[TSZ], g_a3[TSZ];
__device__ float g_ex[TSZ], g_q [TSZ], g_q1[TSZ];
__device__ float g_r [TSZ], g_u [TSZ], g_c [TSZ];
__device__ float g_wf[WTSZ], g_wo[WTSZ];

// ---------------------------------------------------------------------------
// tf32 mma.sync microkernel: 4 warps, warp tile 64x64, block tile 128x128
// smem holds PRE-CONVERTED tf32 bit patterns.
// ---------------------------------------------------------------------------
__device__ __forceinline__ uint32_t f2tf(float f) {
    uint32_t u;
    asm("cvt.rna.tf32.f32 %0, %1;" : "=r"(u) : "f"(f));
    return u;
}
__device__ __forceinline__ uint4 cvt4(float4 v) {
    return make_uint4(f2tf(v.x), f2tf(v.y), f2tf(v.z), f2tf(v.w));
}

__device__ __forceinline__ void mma8(float* d, const uint32_t* a, const uint32_t* b) {
    asm volatile(
        "mma.sync.aligned.m16n8k8.row.col.f32.tf32.tf32.f32 "
        "{%0,%1,%2,%3}, {%4,%5,%6,%7}, {%8,%9}, {%0,%1,%2,%3};\n"
        : "+f"(d[0]), "+f"(d[1]), "+f"(d[2]), "+f"(d[3])
        : "r"(a[0]), "r"(a[1]), "r"(a[2]), "r"(a[3]), "r"(b[0]), "r"(b[1]));
}

// One BK=16 slab for a 64x64 warp tile: 4 m-tiles x 8 n-tiles of m16n8k8
__device__ __forceinline__ void compute64(const uint32_t (*As)[PITCH2],
                                          const uint32_t (*Bs)[PITCH2],
                                          float (*acc)[8][4], int wm, int wn, int lane) {
    int g = lane >> 2, tg = lane & 3;
#pragma unroll
    for (int ks = 0; ks < 2; ++ks) {
        int k0 = ks * 8;
        uint32_t a[4][4], b[8][2];
#pragma unroll
        for (int mt = 0; mt < 4; ++mt) {
            int m = wm + mt * 16 + g;
            a[mt][0] = As[k0 + tg    ][m    ];
            a[mt][1] = As[k0 + tg    ][m + 8];
            a[mt][2] = As[k0 + tg + 4][m    ];
            a[mt][3] = As[k0 + tg + 4][m + 8];
        }
#pragma unroll
        for (int nt = 0; nt < 8; ++nt) {
            int n = wn + nt * 8 + g;
            b[nt][0] = Bs[k0 + tg    ][n];
            b[nt][1] = Bs[k0 + tg + 4][n];
        }
#pragma unroll
        for (int mt = 0; mt < 4; ++mt)
#pragma unroll
            for (int nt = 0; nt < 8; ++nt)
                mma8(acc[mt][nt], a[mt], b[nt]);
    }
}

#define ZERO_ACC(acc)                                       \
    float acc[4][8][4];                                     \
    _Pragma("unroll")                                       \
    for (int i_ = 0; i_ < 4; ++i_)                          \
        _Pragma("unroll")                                   \
        for (int j_ = 0; j_ < 8; ++j_)                      \
            _Pragma("unroll")                               \
            for (int v_ = 0; v_ < 4; ++v_) acc[i_][j_][v_] = 0.f;

#define WARP_COORDS()                                       \
    int t = threadIdx.x, lane = t & 31, wid = t >> 5;       \
    int wm = (wid & 1) * 64, wn = (wid >> 1) * 64;

// ---------------------------------------------------------------------------
// k_scores: S[b,n,m] = sum_c E[b,c,n] * Q[b,c,m]   grid (8,8,16), 128 thr
// ---------------------------------------------------------------------------
__global__ void __launch_bounds__(128) k_scores(const float* __restrict__ E,
                                                const float* __restrict__ Q,
                                                float* __restrict__ S) {
    int b = blockIdx.z;
    const float* Eb = E + (size_t)b * C_ * N_;
    const float* Qb = Q + (size_t)b * C_ * N_;
    float*       Sb = S + (size_t)b * N_ * N_;
    int n0 = blockIdx.y * 128, m0 = blockIdx.x * 128;

    __shared__ uint32_t As[2][16][PITCH2], Bs[2][16][PITCH2];
    WARP_COORDS();
    int lrow = t >> 5, lcol = (t & 31) * 4;   // rows lrow + 4*i, i=0..3

    float4 pa[4], pb[4];
#pragma unroll
    for (int i = 0; i < 4; ++i) {
        int r = lrow + 4 * i;
        pa[i] = *(const float4*)(Eb + (size_t)r * N_ + n0 + lcol);
        pb[i] = *(const float4*)(Qb + (size_t)r * N_ + m0 + lcol);
        *(uint4*)&As[0][r][lcol] = cvt4(pa[i]);
        *(uint4*)&Bs[0][r][lcol] = cvt4(pb[i]);
    }
    __syncthreads();

    ZERO_ACC(acc);
    const int KI = C_ / 16;
    for (int it = 0; it < KI; ++it) {
        int nx = it + 1;
        if (nx < KI) {
#pragma unroll
            for (int i = 0; i < 4; ++i) {
                int r = nx * 16 + lrow + 4 * i;
                pa[i] = *(const float4*)(Eb + (size_t)r * N_ + n0 + lcol);
                pb[i] = *(const float4*)(Qb + (size_t)r * N_ + m0 + lcol);
            }
        }
        compute64(As[it & 1], Bs[it & 1], acc, wm, wn, lane);
        if (nx < KI) {
            int sb = nx & 1;
#pragma unroll
            for (int i = 0; i < 4; ++i) {
                int r = lrow + 4 * i;
                *(uint4*)&As[sb][r][lcol] = cvt4(pa[i]);
                *(uint4*)&Bs[sb][r][lcol] = cvt4(pb[i]);
            }
        }
        __syncthreads();
    }

    int g = lane >> 2, tg = lane & 3;
#pragma unroll
    for (int mt = 0; mt < 4; ++mt)
#pragma unroll
        for (int nt = 0; nt < 8; ++nt) {
            int row = n0 + wm + mt * 16 + g;
            int col = m0 + wn + nt * 8 + tg * 2;
            *(float2*)(Sb + (size_t)row * N_ + col)       = make_float2(acc[mt][nt][0], acc[mt][nt][1]);
            *(float2*)(Sb + (size_t)(row + 8) * N_ + col) = make_float2(acc[mt][nt][2], acc[mt][nt][3]);
        }
}

// ---------------------------------------------------------------------------
// Row softmax over m. grid = B_*N_, 256 threads
// ---------------------------------------------------------------------------
__global__ void __launch_bounds__(256) k_softmax(float* __restrict__ S) {
    float* row = S + (size_t)blockIdx.x * N_;
    int t = threadIdx.x;
    float4 v = *(float4*)(row + 4 * t);
    __shared__ float red[8];

    float m = fmaxf(fmaxf(v.x, v.y), fmaxf(v.z, v.w));
#pragma unroll
    for (int o = 16; o; o >>= 1) m = fmaxf(m, __shfl_xor_sync(0xffffffffu, m, o));
    if ((t & 31) == 0) red[t >> 5] = m;
    __syncthreads();
    float mx = red[0];
#pragma unroll
    for (int i = 1; i < 8; ++i) mx = fmaxf(mx, red[i]);
    __syncthreads();

    v.x = __expf(v.x - mx); v.y = __expf(v.y - mx);
    v.z = __expf(v.z - mx); v.w = __expf(v.w - mx);
    float s = v.x + v.y + v.z + v.w;
#pragma unroll
    for (int o = 16; o; o >>= 1) s += __shfl_xor_sync(0xffffffffu, s, o);
    if ((t & 31) == 0) red[t >> 5] = s;
    __syncthreads();
    float tot = red[0];
#pragma unroll
    for (int i = 1; i < 8; ++i) tot += red[i];
    float inv = 1.f / tot;
    v.x *= inv; v.y *= inv; v.z *= inv; v.w *= inv;
    *(float4*)(row + 4 * t) = v;
}

// ---------------------------------------------------------------------------
// k_attmm: O[b,c,n] = sum_m Q[b,c,m] * S[b,n,m]   grid (8,4,16), 128 thr
// Both operands transposed into smem (k-major).
// ---------------------------------------------------------------------------
__global__ void __launch_bounds__(128) k_attmm(const float* __restrict__ Q,
                                               const float* __restrict__ S,
                                               float* __restrict__ O) {
    int b = blockIdx.z;
    const float* Qb = Q + (size_t)b * C_ * N_;
    const float* Sb = S + (size_t)b * N_ * N_;
    float*       Ob = O + (size_t)b * C_ * N_;
    int c0 = blockIdx.y * 128, n0 = blockIdx.x * 128;

    __shared__ uint32_t As[2][16][PITCH2], Bs[2][16][PITCH2];
    WARP_COORDS();

    float4 pa[4], pb[4];
    auto ldAB = [&](int k0) {
#pragma unroll
        for (int i = 0; i < 4; ++i) {
            pa[i] = *(const float4*)(Qb + (size_t)(c0 + t) * N_ + k0 + 4 * i);
            pb[i] = *(const float4*)(Sb + (size_t)(n0 + t) * N_ + k0 + 4 * i);
        }
    };
    auto stAB = [&](int sb) {
#pragma unroll
        for (int i = 0; i < 4; ++i)
#pragma unroll
            for (int j = 0; j < 4; ++j) {
                As[sb][4 * i + j][t] = f2tf((&pa[i].x)[j]);
                Bs[sb][4 * i + j][t] = f2tf((&pb[i].x)[j]);
            }
    };

    ldAB(0); stAB(0);
    __syncthreads();

    ZERO_ACC(acc);
    const int KI = N_ / 16;
    for (int it = 0; it < KI; ++it) {
        int nx = it + 1;
        if (nx < KI) ldAB(nx * 16);
        compute64(As[it & 1], Bs[it & 1], acc, wm, wn, lane);
        if (nx < KI) stAB(nx & 1);
        __syncthreads();
    }

    int g = lane >> 2, tg = lane & 3;
#pragma unroll
    for (int mt = 0; mt < 4; ++mt)
#pragma unroll
        for (int nt = 0; nt < 8; ++nt) {
            int row = c0 + wm + mt * 16 + g;
            int col = n0 + wn + nt * 8 + tg * 2;
            *(float2*)(Ob + (size_t)row * N_ + col)       = make_float2(acc[mt][nt][0], acc[mt][nt][1]);
            *(float2*)(Ob + (size_t)(row + 8) * N_ + col) = make_float2(acc[mt][nt][2], acc[mt][nt][3]);
        }
}

// ---------------------------------------------------------------------------
// k_gemm1x1: Y = act(W @ [X0;X1] + bias). grid (8,4,16), 128 thr
// ---------------------------------------------------------------------------
__global__ void __launch_bounds__(128) k_gemm1x1(const float* __restrict__ W,
                                                 const float* __restrict__ X0,
                                                 const float* __restrict__ X1,
                                                 const float* __restrict__ bias,
                                                 float* __restrict__ Y, int act) {
    int b = blockIdx.z;
    const float* x0 = X0 + (size_t)b * C_ * N_;
    const float* x1 = X1 + (size_t)b * C_ * N_;
    float*       Yb = Y  + (size_t)b * C_ * N_;
    int co0 = blockIdx.y * 128, p0 = blockIdx.x * 128;

    __shared__ uint32_t As[2][16][PITCH2], Bs[2][16][PITCH2];
    WARP_COORDS();
    int brow = t >> 5, bcol = (t & 31) * 4;

    float4 pa[4], pb[4];
    auto ldA = [&](int k0) {
#pragma unroll
        for (int i = 0; i < 4; ++i)
            pa[i] = *(const float4*)(W + (size_t)(co0 + t) * (2 * C_) + k0 + 4 * i);
    };
    auto ldB = [&](int k0) {
#pragma unroll
        for (int i = 0; i < 4; ++i) {
            int ci = k0 + brow + 4 * i;
            const float* src = (ci < C_) ? (x0 + (size_t)ci * N_) : (x1 + (size_t)(ci - C_) * N_);
            pb[i] = *(const float4*)(src + p0 + bcol);
        }
    };
    auto stAB = [&](int sb) {
#pragma unroll
        for (int i = 0; i < 4; ++i) {
#pragma unroll
            for (int j = 0; j < 4; ++j)
                As[sb][4 * i + j][t] = f2tf((&pa[i].x)[j]);
            *(uint4*)&Bs[sb][brow + 4 * i][bcol] = cvt4(pb[i]);
        }
    };

    ldA(0); ldB(0); stAB(0);
    __syncthreads();

    ZERO_ACC(acc);
    const int KI = (2 * C_) / 16;
    for (int it = 0; it < KI; ++it) {
        int nx = it + 1;
        if (nx < KI) { ldA(nx * 16); ldB(nx * 16); }
        compute64(As[it & 1], Bs[it & 1], acc, wm, wn, lane);
        if (nx < KI) stAB(nx & 1);
        __syncthreads();
    }

    int g = lane >> 2, tg = lane & 3;
#pragma unroll
    for (int mt = 0; mt < 4; ++mt)
#pragma unroll
        for (int nt = 0; nt < 8; ++nt) {
            int row = co0 + wm + mt * 16 + g;
            int col = p0 + wn + nt * 8 + tg * 2;
            float bv0 = bias[row], bv1 = bias[row + 8];
            float o[4] = {acc[mt][nt][0] + bv0, acc[mt][nt][1] + bv0,
                          acc[mt][nt][2] + bv1, acc[mt][nt][3] + bv1};
#pragma unroll
            for (int v = 0; v < 4; ++v) {
                if (act == 1)      o[v] = 1.f / (1.f + __expf(-o[v]));
                else if (act == 2) o[v] = tanhf(o[v]);
            }
            *(float2*)(Yb + (size_t)row * N_ + col)       = make_float2(o[0], o[1]);
            *(float2*)(Yb + (size_t)(row + 8) * N_ + col) = make_float2(o[2], o[3]);
        }
}

// ---------------------------------------------------------------------------
// k_conv3: 3x3 conv pad 1, implicit GEMM, K = 9*1024. grid (8,4,16), 128 thr
// Wt layout: [tap][co][ci]
// ---------------------------------------------------------------------------
__global__ void __launch_bounds__(128) k_conv3(const float* __restrict__ Wt,
                                               const float* __restrict__ X0,
                                               const float* __restrict__ X1,
                                               const float* __restrict__ bias,
                                               float* __restrict__ Y) {
    int b = blockIdx.z;
    const float* x0 = X0 + (size_t)b * C_ * N_;
    const float* x1 = X1 + (size_t)b * C_ * N_;
    float*       Yb = Y  + (size_t)b * C_ * N_;
    int co0 = blockIdx.y * 128, p0 = blockIdx.x * 128;

    __shared__ uint32_t As[2][16][PITCH2], Bs[2][16][PITCH2];
    WARP_COORDS();
    int brow = t >> 5, bcol = (t & 31) * 4;

    float4 pa[4], pb[4];
    auto ldA = [&](int it) {
        int tap = it >> 6, k0 = (it & 63) * 16;
        const float* wrow = Wt + (size_t)tap * C_ * (2 * C_)
                          + (size_t)(co0 + t) * (2 * C_) + k0;
#pragma unroll
        for (int i = 0; i < 4; ++i) pa[i] = *(const float4*)(wrow + 4 * i);
    };
    auto ldB = [&](int it) {
        int tap = it >> 6, k0 = (it & 63) * 16;
        int dy = tap / 3 - 1, dx = tap % 3 - 1;
#pragma unroll
        for (int i = 0; i < 4; ++i) {
            int ci = k0 + brow + 4 * i;
            const float* src = (ci < C_) ? (x0 + (size_t)ci * N_) : (x1 + (size_t)(ci - C_) * N_);
            float v[4];
#pragma unroll
            for (int j = 0; j < 4; ++j) {
                int p = p0 + bcol + j;
                int y = (p >> 5) + dy;
                int x = (p & 31) + dx;
                v[j] = ((unsigned)y < HW && (unsigned)x < HW) ? src[y * HW + x] : 0.f;
            }
            pb[i] = make_float4(v[0], v[1], v[2], v[3]);
        }
    };
    auto stAB = [&](int sb) {
#pragma unroll
        for (int i = 0; i < 4; ++i) {
#pragma unroll
            for (int j = 0; j < 4; ++j)
                As[sb][4 * i + j][t] = f2tf((&pa[i].x)[j]);
            *(uint4*)&Bs[sb][brow + 4 * i][bcol] = cvt4(pb[i]);
        }
    };

    ldA(0); ldB(0); stAB(0);
    __syncthreads();

    ZERO_ACC(acc);
    const int KI = 9 * (2 * C_) / 16;   // 576
    for (int it = 0; it < KI; ++it) {
        int nx = it + 1;
        if (nx < KI) { ldA(nx); ldB(nx); }
        compute64(As[it & 1], Bs[it & 1], acc, wm, wn, lane);
        if (nx < KI) stAB(nx & 1);
        __syncthreads();
    }

    int g = lane >> 2, tg = lane & 3;
#pragma unroll
    for (int mt = 0; mt < 4; ++mt)
#pragma unroll
        for (int nt = 0; nt < 8; ++nt) {
            int row = co0 + wm + mt * 16 + g;
            int col = p0 + wn + nt * 8 + tg * 2;
            float bv0 = bias[row], bv1 = bias[row + 8];
            *(float2*)(Yb + (size_t)row * N_ + col)       = make_float2(acc[mt][nt][0] + bv0, acc[mt][nt][1] + bv0);
            *(float2*)(Yb + (size_t)(row + 8) * N_ + col) = make_float2(acc[mt][nt][2] + bv1, acc[mt][nt][3] + bv1);
        }
}

// ---------------------------------------------------------------------------
// Small utility kernels
// ---------------------------------------------------------------------------
__global__ void k_wt(const float* __restrict__ w, float* __restrict__ wt) {
    size_t i = (size_t)blockIdx.x * 256 + threadIdx.x;
    if (i >= WTSZ) return;
    int ci  = (int)(i % (2 * C_));
    int co  = (int)((i / (2 * C_)) % C_);
    int tap = (int)(i / ((size_t)C_ * 2 * C_));
    wt[i] = w[((size_t)co * (2 * C_) + ci) * 9 + tap];
}

__global__ void k_init(const float* __restrict__ a, const float* __restrict__ b,
                       const float* __restrict__ c) {
    size_t i = ((size_t)blockIdx.x * 256 + threadIdx.x) * 4;
    *(float4*)(g_ex + i) = *(const float4*)(a + i);
    *(float4*)(g_q  + i) = *(const float4*)(b + i);
    *(float4*)(g_q1 + i) = *(const float4*)(c + i);
}

__global__ void k_mul(float* __restrict__ r, const float* __restrict__ h) {
    size_t i = ((size_t)blockIdx.x * 256 + threadIdx.x) * 4;
    float4 a = *(float4*)(r + i);
    float4 b = *(const float4*)(h + i);
    a.x *= b.x; a.y *= b.y; a.z *= b.z; a.w *= b.w;
    *(float4*)(r + i) = a;
}

__global__ void k_gruout(float* __restrict__ h, const float* __restrict__ u,
                         const float* __restrict__ c) {
    size_t i = ((size_t)blockIdx.x * 256 + threadIdx.x) * 4;
    float4 hv = *(float4*)(h + i);
    float4 uv = *(const float4*)(u + i);
    float4 cv = *(const float4*)(c + i);
    hv.x = hv.x * (1.f - uv.x) + cv.x * uv.x;
    hv.y = hv.y * (1.f - uv.y) + cv.y * uv.y;
    hv.z = hv.z * (1.f - uv.z) + cv.z * uv.z;
    hv.w = hv.w * (1.f - uv.w) + cv.w * uv.w;
    *(float4*)(h + i) = hv;
}

// ---------------------------------------------------------------------------
// Host orchestration
// ---------------------------------------------------------------------------
static void attention(const float* Xe, const float* Xq, float* O, float* Sbuf) {
    k_scores<<<dim3(8, 8, B_), 128>>>(Xe, Xq, Sbuf);
    k_softmax<<<B_ * N_, 256>>>(Sbuf);
    k_attmm<<<dim3(8, 4, B_), 128>>>(Xq, Sbuf, O);
}

extern "C" void kernel_launch(void* const* d_in, const int* in_sizes, int n_in,
                              void* d_out, int out_size) {
    const float* in1      = (const float*)d_in[0];
    const float* in2      = (const float*)d_in[1];
    const float* in3      = (const float*)d_in[2];
    const float* w_fusion = (const float*)d_in[3];
    const float* b_fusion = (const float*)d_in[4];
    const float* w_out    = (const float*)d_in[5];
    const float* b_out    = (const float*)d_in[6];
    const float* w_reset  = (const float*)d_in[7];
    const float* b_reset  = (const float*)d_in[8];
    const float* w_update = (const float*)d_in[9];
    const float* b_update = (const float*)d_in[10];
    const float* w_cand   = (const float*)d_in[11];
    const float* b_cand   = (const float*)d_in[12];
    float* out = (float*)d_out;

    float *S, *O1, *O2, *a1, *a2, *a3, *ex, *q, *q1, *r, *u, *c, *wf, *wo;
    cudaGetSymbolAddress((void**)&S,  g_S);
    cudaGetSymbolAddress((void**)&O1, g_O1);
    cudaGetSymbolAddress((void**)&O2, g_O2);
    cudaGetSymbolAddress((void**)&a1, g_a1);
    cudaGetSymbolAddress((void**)&a2, g_a2);
    cudaGetSymbolAddress((void**)&a3, g_a3);
    cudaGetSymbolAddress((void**)&ex, g_ex);
    cudaGetSymbolAddress((void**)&q,  g_q);
    cudaGetSymbolAddress((void**)&q1, g_q1);
    cudaGetSymbolAddress((void**)&r,  g_r);
    cudaGetSymbolAddress((void**)&u,  g_u);
    cudaGetSymbolAddress((void**)&c,  g_c);
    cudaGetSymbolAddress((void**)&wf, g_wf);
    cudaGetSymbolAddress((void**)&wo, g_wo);

    const int EWG = (int)(TSZ / 4 / 256);
    const int WTG = (int)((WTSZ + 255) / 256);

    k_init<<<EWG, 256>>>(in1, in2, in3);
    k_wt<<<WTG, 256>>>(w_fusion, wf);
    k_wt<<<WTG, 256>>>(w_out, wo);

    dim3 gA(8, 4, B_);
    for (int round = 0; round < 5; ++round) {
        attention(ex, q,  O1, S);
        attention(ex, q1, O2, S);
        k_conv3<<<gA, 128>>>(wf, O1, O2, b_fusion, a1);

        attention(q, ex, O1, S);
        attention(q, q1, O2, S);
        k_conv3<<<gA, 128>>>(wf, O1, O2, b_fusion, a2);

        attention(q1, ex, O1, S);
        attention(q1, q,  O2, S);
        k_conv3<<<gA, 128>>>(wf, O1, O2, b_fusion, a3);

        float* xs[3] = {a1, a2, a3};
        float* hs[3] = {ex, q, q1};
        for (int s = 0; s < 3; ++s) {
            k_gemm1x1<<<gA, 128>>>(w_reset,  xs[s], hs[s], b_reset,  r, 1);
            k_gemm1x1<<<gA, 128>>>(w_update, xs[s], hs[s], b_update, u, 1);
            k_mul<<<EWG, 256>>>(r, hs[s]);
            k_gemm1x1<<<gA, 128>>>(w_cand, xs[s], r, b_cand, c, 2);
            k_gruout<<<EWG, 256>>>(hs[s], u, c);
        }
    }

    k_conv3<<<gA, 128>>>(wo, ex, in1, b_out, out);
    k_conv3<<<gA, 128>>>(wo, q,  in2, b_out, out + TSZ);
    k_conv3<<<gA, 128>>>(wo, q1, in3, b_out, out + 2 * TSZ);
}

// round 5
// speedup vs baseline: 3.2334x; 1.2726x over previous
#include <cuda_runtime.h>
#include <cuda_fp16.h>
#include <math.h>
#include <stdint.h>

// ---------------------------------------------------------------------------
// Problem constants
// ---------------------------------------------------------------------------
#define B_  16
#define C_  512
#define N_  1024
#define HW  32
#define SPITCH 12   // smem row stride in u32 (8 used + 4 pad): conflict-free

static constexpr size_t TSZ  = (size_t)B_ * C_ * N_;
static constexpr size_t WTSZ = (size_t)9 * C_ * (2 * C_);

// ---------------------------------------------------------------------------
// Scratch (static device globals; no allocation anywhere)
// ---------------------------------------------------------------------------
__device__ float g_S [(size_t)B_ * N_ * N_];
__device__ float g_O1[TSZ], g_O2[TSZ];
__device__ float g_a1[TSZ], g_a2[TSZ], g_a3[TSZ];
__device__ float g_ex[TSZ], g_q [TSZ], g_q1[TSZ];
__device__ float g_r [TSZ], g_u [TSZ], g_c [TSZ];
__device__ float g_exT[TSZ], g_qT[TSZ], g_q1T[TSZ];      // [b][n][c]
__device__ float g_a1T[TSZ], g_a2T[TSZ], g_a3T[TSZ];     // [b][p][co]
__device__ float g_wf[WTSZ], g_wo[WTSZ];                 // [tap][co][ci]
__device__ float g_wru[(size_t)2 * C_ * 2 * C_];         // concat reset|update

// ---------------------------------------------------------------------------
// fp16 mma.sync microkernel: 4 warps, warp tile 64x64, block tile 128x128
// smem holds half2-packed operands, layout [row][kpair], stride SPITCH u32.
// ---------------------------------------------------------------------------
__device__ __forceinline__ uint32_t h2(float lo, float hi) {
    __half2 h = __floats2half2_rn(lo, hi);
    return *(uint32_t*)&h;
}

__device__ __forceinline__ void mma16(float* d, const uint32_t* a, const uint32_t* b) {
    asm volatile(
        "mma.sync.aligned.m16n8k16.row.col.f32.f16.f16.f32 "
        "{%0,%1,%2,%3}, {%4,%5,%6,%7}, {%8,%9}, {%0,%1,%2,%3};\n"
        : "+f"(d[0]), "+f"(d[1]), "+f"(d[2]), "+f"(d[3])
        : "r"(a[0]), "r"(a[1]), "r"(a[2]), "r"(a[3]), "r"(b[0]), "r"(b[1]));
}

// One K=16 slab, warp tile 64x64: 4 m-tiles x 8 n-tiles of m16n8k16
__device__ __forceinline__ void compute16(const uint32_t (*As)[SPITCH],
                                          const uint32_t (*Bs)[SPITCH],
                                          float (*acc)[8][4], int wm, int wn,
                                          int g, int tg) {
    uint32_t a[4][4], b[8][2];
#pragma unroll
    for (int mt = 0; mt < 4; ++mt) {
        int m = wm + mt * 16 + g;
        a[mt][0] = As[m][tg];     a[mt][1] = As[m + 8][tg];
        a[mt][2] = As[m][tg + 4]; a[mt][3] = As[m + 8][tg + 4];
    }
#pragma unroll
    for (int nt = 0; nt < 8; ++nt) {
        int n = wn + nt * 8 + g;
        b[nt][0] = Bs[n][tg]; b[nt][1] = Bs[n][tg + 4];
    }
#pragma unroll
    for (int mt = 0; mt < 4; ++mt)
#pragma unroll
        for (int nt = 0; nt < 8; ++nt)
            mma16(acc[mt][nt], a[mt], b[nt]);
}

#define ZERO_ACC(acc)                                       \
    float acc[4][8][4];                                     \
    _Pragma("unroll")                                       \
    for (int i_ = 0; i_ < 4; ++i_)                          \
        _Pragma("unroll")                                   \
        for (int j_ = 0; j_ < 8; ++j_)                      \
            _Pragma("unroll")                               \
            for (int v_ = 0; v_ < 4; ++v_) acc[i_][j_][v_] = 0.f;

#define WARP_COORDS()                                       \
    int t = threadIdx.x, lane = t & 31, wid = t >> 5;       \
    int wm = (wid & 1) * 64, wn = (wid >> 1) * 64;          \
    int g = lane >> 2, tg = lane & 3;

// Staging register buffer: 16 fp32 values = one smem row (one thread per row)
struct Stage { float v[16]; };

__device__ __forceinline__ void ld_contig(Stage& s, const float* __restrict__ p) {
#pragma unroll
    for (int i = 0; i < 4; ++i) {
        float4 f = *(const float4*)(p + 4 * i);
        s.v[4 * i] = f.x; s.v[4 * i + 1] = f.y; s.v[4 * i + 2] = f.z; s.v[4 * i + 3] = f.w;
    }
}

__device__ __forceinline__ void st_row(const Stage& s, uint32_t (*M)[SPITCH], int row) {
    uint4 w0 = make_uint4(h2(s.v[0], s.v[1]),  h2(s.v[2], s.v[3]),
                          h2(s.v[4], s.v[5]),  h2(s.v[6], s.v[7]));
    uint4 w1 = make_uint4(h2(s.v[8], s.v[9]),  h2(s.v[10], s.v[11]),
                          h2(s.v[12], s.v[13]), h2(s.v[14], s.v[15]));
    *(uint4*)&M[row][0] = w0;
    *(uint4*)&M[row][4] = w1;
}

// ---------------------------------------------------------------------------
// k_scores: S[b,n,m] = sum_c ET[n,c] * QT[m,c].  grid (8,8,16), 128 thr
// Both operands contiguous rows from transposed state copies.
// ---------------------------------------------------------------------------
__global__ void __launch_bounds__(128, 2) k_scores(const float* __restrict__ ET,
                                                   const float* __restrict__ QT,
                                                   float* __restrict__ S) {
    int b = blockIdx.z;
    const float* At = ET + (size_t)b * N_ * C_;
    const float* Bt = QT + (size_t)b * N_ * C_;
    float*       Sb = S  + (size_t)b * N_ * N_;
    int n0 = blockIdx.y * 128, m0 = blockIdx.x * 128;

    __shared__ uint32_t As[2][128][SPITCH], Bs[2][128][SPITCH];
    WARP_COORDS();

    Stage sa, sb;
    ld_contig(sa, At + (size_t)(n0 + t) * C_);
    ld_contig(sb, Bt + (size_t)(m0 + t) * C_);
    st_row(sa, As[0], t); st_row(sb, Bs[0], t);
    __syncthreads();

    ZERO_ACC(acc);
    const int KI = C_ / 16;   // 32
    for (int it = 0; it < KI; ++it) {
        int nx = it + 1;
        if (nx < KI) {
            ld_contig(sa, At + (size_t)(n0 + t) * C_ + nx * 16);
            ld_contig(sb, Bt + (size_t)(m0 + t) * C_ + nx * 16);
        }
        compute16(As[it & 1], Bs[it & 1], acc, wm, wn, g, tg);
        if (nx < KI) { st_row(sa, As[nx & 1], t); st_row(sb, Bs[nx & 1], t); }
        __syncthreads();
    }

#pragma unroll
    for (int mt = 0; mt < 4; ++mt)
#pragma unroll
        for (int nt = 0; nt < 8; ++nt) {
            int row = n0 + wm + mt * 16 + g;
            int col = m0 + wn + nt * 8 + tg * 2;
            *(float2*)(Sb + (size_t)row * N_ + col)       = make_float2(acc[mt][nt][0], acc[mt][nt][1]);
            *(float2*)(Sb + (size_t)(row + 8) * N_ + col) = make_float2(acc[mt][nt][2], acc[mt][nt][3]);
        }
}

// ---------------------------------------------------------------------------
// Row softmax over m. grid = B_*N_, 256 threads
// ---------------------------------------------------------------------------
__global__ void __launch_bounds__(256) k_softmax(float* __restrict__ S) {
    float* row = S + (size_t)blockIdx.x * N_;
    int t = threadIdx.x;
    float4 v = *(float4*)(row + 4 * t);
    __shared__ float red[8];

    float m = fmaxf(fmaxf(v.x, v.y), fmaxf(v.z, v.w));
#pragma unroll
    for (int o = 16; o; o >>= 1) m = fmaxf(m, __shfl_xor_sync(0xffffffffu, m, o));
    if ((t & 31) == 0) red[t >> 5] = m;
    __syncthreads();
    float mx = red[0];
#pragma unroll
    for (int i = 1; i < 8; ++i) mx = fmaxf(mx, red[i]);
    __syncthreads();

    v.x = __expf(v.x - mx); v.y = __expf(v.y - mx);
    v.z = __expf(v.z - mx); v.w = __expf(v.w - mx);
    float s = v.x + v.y + v.z + v.w;
#pragma unroll
    for (int o = 16; o; o >>= 1) s += __shfl_xor_sync(0xffffffffu, s, o);
    if ((t & 31) == 0) red[t >> 5] = s;
    __syncthreads();
    float tot = red[0];
#pragma unroll
    for (int i = 1; i < 8; ++i) tot += red[i];
    float inv = 1.f / tot;
    v.x *= inv; v.y *= inv; v.z *= inv; v.w *= inv;
    *(float4*)(row + 4 * t) = v;
}

// ---------------------------------------------------------------------------
// k_attmm: O[b,c,n] = sum_m Q[c,m] * S[n,m].  grid (8,4,16), 128 thr
// Both operands contiguous rows (Q normal layout, S rows).
// ---------------------------------------------------------------------------
__global__ void __launch_bounds__(128, 2) k_attmm(const float* __restrict__ Q,
                                                  const float* __restrict__ S,
                                                  float* __restrict__ O) {
    int b = blockIdx.z;
    const float* Qb = Q + (size_t)b * C_ * N_;
    const float* Sb = S + (size_t)b * N_ * N_;
    float*       Ob = O + (size_t)b * C_ * N_;
    int c0 = blockIdx.y * 128, n0 = blockIdx.x * 128;

    __shared__ uint32_t As[2][128][SPITCH], Bs[2][128][SPITCH];
    WARP_COORDS();

    Stage sa, sb;
    ld_contig(sa, Qb + (size_t)(c0 + t) * N_);
    ld_contig(sb, Sb + (size_t)(n0 + t) * N_);
    st_row(sa, As[0], t); st_row(sb, Bs[0], t);
    __syncthreads();

    ZERO_ACC(acc);
    const int KI = N_ / 16;   // 64
    for (int it = 0; it < KI; ++it) {
        int nx = it + 1;
        if (nx < KI) {
            ld_contig(sa, Qb + (size_t)(c0 + t) * N_ + nx * 16);
            ld_contig(sb, Sb + (size_t)(n0 + t) * N_ + nx * 16);
        }
        compute16(As[it & 1], Bs[it & 1], acc, wm, wn, g, tg);
        if (nx < KI) { st_row(sa, As[nx & 1], t); st_row(sb, Bs[nx & 1], t); }
        __syncthreads();
    }

#pragma unroll
    for (int mt = 0; mt < 4; ++mt)
#pragma unroll
        for (int nt = 0; nt < 8; ++nt) {
            int row = c0 + wm + mt * 16 + g;
            int col = n0 + wn + nt * 8 + tg * 2;
            *(float2*)(Ob + (size_t)row * N_ + col)       = make_float2(acc[mt][nt][0], acc[mt][nt][1]);
            *(float2*)(Ob + (size_t)(row + 8) * N_ + col) = make_float2(acc[mt][nt][2], acc[mt][nt][3]);
        }
}

// ---------------------------------------------------------------------------
// k_gemmRU: fused reset+update. M=1024 (rows 0-511 -> r, 512-1023 -> u),
// K=1024 with B = [x(aT) ; h(hT)], both contiguous. grid (8,8,16)
// ---------------------------------------------------------------------------
__global__ void __launch_bounds__(128, 2) k_gemmRU(const float* __restrict__ Wru,
                                                   const float* __restrict__ xT,
                                                   const float* __restrict__ hT,
                                                   const float* __restrict__ b_r,
                                                   const float* __restrict__ b_u,
                                                   float* __restrict__ R,
                                                   float* __restrict__ U) {
    int b = blockIdx.z;
    const float* xTb = xT + (size_t)b * N_ * C_;
    const float* hTb = hT + (size_t)b * N_ * C_;
    int co0 = blockIdx.y * 128, p0 = blockIdx.x * 128;

    __shared__ uint32_t As[2][128][SPITCH], Bs[2][128][SPITCH];
    WARP_COORDS();

    Stage sa, sb;
    auto ldB = [&](int ci0) {
        const float* src = (ci0 < C_) ? (xTb + (size_t)(p0 + t) * C_ + ci0)
                                      : (hTb + (size_t)(p0 + t) * C_ + (ci0 - C_));
        ld_contig(sb, src);
    };
    ld_contig(sa, Wru + (size_t)(co0 + t) * (2 * C_));
    ldB(0);
    st_row(sa, As[0], t); st_row(sb, Bs[0], t);
    __syncthreads();

    ZERO_ACC(acc);
    const int KI = (2 * C_) / 16;   // 64
    for (int it = 0; it < KI; ++it) {
        int nx = it + 1;
        if (nx < KI) {
            ld_contig(sa, Wru + (size_t)(co0 + t) * (2 * C_) + nx * 16);
            ldB(nx * 16);
        }
        compute16(As[it & 1], Bs[it & 1], acc, wm, wn, g, tg);
        if (nx < KI) { st_row(sa, As[nx & 1], t); st_row(sb, Bs[nx & 1], t); }
        __syncthreads();
    }

    bool isR = co0 < C_;
    float* dst = (isR ? R : U) + (size_t)b * C_ * N_;
    int rbase = isR ? co0 : (co0 - C_);
    const float* bias = isR ? b_r : b_u;
#pragma unroll
    for (int mt = 0; mt < 4; ++mt)
#pragma unroll
        for (int nt = 0; nt < 8; ++nt) {
            int row = rbase + wm + mt * 16 + g;
            int col = p0 + wn + nt * 8 + tg * 2;
            float bv0 = bias[row], bv1 = bias[row + 8];
            float o0 = 1.f / (1.f + __expf(-(acc[mt][nt][0] + bv0)));
            float o1 = 1.f / (1.f + __expf(-(acc[mt][nt][1] + bv0)));
            float o2 = 1.f / (1.f + __expf(-(acc[mt][nt][2] + bv1)));
            float o3 = 1.f / (1.f + __expf(-(acc[mt][nt][3] + bv1)));
            *(float2*)(dst + (size_t)row * N_ + col)       = make_float2(o0, o1);
            *(float2*)(dst + (size_t)(row + 8) * N_ + col) = make_float2(o2, o3);
        }
}

// ---------------------------------------------------------------------------
// k_gemmCAND: c = tanh(Wc @ [x ; r*h] + b). B first half contiguous (aT),
// second half = r*h computed at staging (strided). grid (8,4,16)
// ---------------------------------------------------------------------------
__global__ void __launch_bounds__(128, 2) k_gemmCAND(const float* __restrict__ Wc,
                                                     const float* __restrict__ xT,
                                                     const float* __restrict__ R,
                                                     const float* __restrict__ H,
                                                     const float* __restrict__ bias,
                                                     float* __restrict__ Y) {
    int b = blockIdx.z;
    const float* xTb = xT + (size_t)b * N_ * C_;
    const float* Rb  = R  + (size_t)b * C_ * N_;
    const float* Hb  = H  + (size_t)b * C_ * N_;
    float*       Yb  = Y  + (size_t)b * C_ * N_;
    int co0 = blockIdx.y * 128, p0 = blockIdx.x * 128;

    __shared__ uint32_t As[2][128][SPITCH], Bs[2][128][SPITCH];
    WARP_COORDS();

    Stage sa, sb;
    auto ldB = [&](int ci0) {
        if (ci0 < C_) {
            ld_contig(sb, xTb + (size_t)(p0 + t) * C_ + ci0);
        } else {
            int ch = ci0 - C_;
            const float* rp = Rb + (size_t)ch * N_ + p0 + t;
            const float* hp = Hb + (size_t)ch * N_ + p0 + t;
#pragma unroll
            for (int k = 0; k < 16; ++k)
                sb.v[k] = rp[(size_t)k * N_] * hp[(size_t)k * N_];
        }
    };
    ld_contig(sa, Wc + (size_t)(co0 + t) * (2 * C_));
    ldB(0);
    st_row(sa, As[0], t); st_row(sb, Bs[0], t);
    __syncthreads();

    ZERO_ACC(acc);
    const int KI = (2 * C_) / 16;
    for (int it = 0; it < KI; ++it) {
        int nx = it + 1;
        if (nx < KI) {
            ld_contig(sa, Wc + (size_t)(co0 + t) * (2 * C_) + nx * 16);
            ldB(nx * 16);
        }
        compute16(As[it & 1], Bs[it & 1], acc, wm, wn, g, tg);
        if (nx < KI) { st_row(sa, As[nx & 1], t); st_row(sb, Bs[nx & 1], t); }
        __syncthreads();
    }

#pragma unroll
    for (int mt = 0; mt < 4; ++mt)
#pragma unroll
        for (int nt = 0; nt < 8; ++nt) {
            int row = co0 + wm + mt * 16 + g;
            int col = p0 + wn + nt * 8 + tg * 2;
            float bv0 = bias[row], bv1 = bias[row + 8];
            *(float2*)(Yb + (size_t)row * N_ + col) =
                make_float2(tanhf(acc[mt][nt][0] + bv0), tanhf(acc[mt][nt][1] + bv0));
            *(float2*)(Yb + (size_t)(row + 8) * N_ + col) =
                make_float2(tanhf(acc[mt][nt][2] + bv1), tanhf(acc[mt][nt][3] + bv1));
        }
}

// ---------------------------------------------------------------------------
// k_conv3: 3x3 conv pad 1, implicit GEMM K=9*1024.  grid (8,4,16), 128 thr
// A = Wt[tap][co][ci] contiguous; B = gathered shifted pixels (strided).
// ---------------------------------------------------------------------------
__global__ void __launch_bounds__(128, 2) k_conv3(const float* __restrict__ Wt,
                                                  const float* __restrict__ X0,
                                                  const float* __restrict__ X1,
                                                  const float* __restrict__ bias,
                                                  float* __restrict__ Y) {
    int b = blockIdx.z;
    const float* x0 = X0 + (size_t)b * C_ * N_;
    const float* x1 = X1 + (size_t)b * C_ * N_;
    float*       Yb = Y  + (size_t)b * C_ * N_;
    int co0 = blockIdx.y * 128, p0 = blockIdx.x * 128;

    __shared__ uint32_t As[2][128][SPITCH], Bs[2][128][SPITCH];
    WARP_COORDS();

    int p = p0 + t;
    int py = p >> 5, px = p & 31;

    Stage sa, sb;
    auto ldA = [&](int it) {
        int tap = it >> 6, ci0 = (it & 63) * 16;
        ld_contig(sa, Wt + (size_t)tap * C_ * (2 * C_)
                         + (size_t)(co0 + t) * (2 * C_) + ci0);
    };
    auto ldB = [&](int it) {
        int tap = it >> 6, ci0 = (it & 63) * 16;
        int dy = tap / 3 - 1, dx = tap % 3 - 1;
        int y = py + dy, x = px + dx;
        bool ok = ((unsigned)y < HW) && ((unsigned)x < HW);
        const float* src = (ci0 < C_) ? (x0 + (size_t)ci0 * N_)
                                      : (x1 + (size_t)(ci0 - C_) * N_);
        const float* pp = src + y * HW + x;
#pragma unroll
        for (int k = 0; k < 16; ++k)
            sb.v[k] = ok ? pp[(size_t)k * N_] : 0.f;
    };

    ldA(0); ldB(0);
    st_row(sa, As[0], t); st_row(sb, Bs[0], t);
    __syncthreads();

    ZERO_ACC(acc);
    const int KI = 9 * (2 * C_) / 16;   // 576
    for (int it = 0; it < KI; ++it) {
        int nx = it + 1;
        if (nx < KI) { ldA(nx); ldB(nx); }
        compute16(As[it & 1], Bs[it & 1], acc, wm, wn, g, tg);
        if (nx < KI) { st_row(sa, As[nx & 1], t); st_row(sb, Bs[nx & 1], t); }
        __syncthreads();
    }

#pragma unroll
    for (int mt = 0; mt < 4; ++mt)
#pragma unroll
        for (int nt = 0; nt < 8; ++nt) {
            int row = co0 + wm + mt * 16 + g;
            int col = p0 + wn + nt * 8 + tg * 2;
            float bv0 = bias[row], bv1 = bias[row + 8];
            *(float2*)(Yb + (size_t)row * N_ + col)       = make_float2(acc[mt][nt][0] + bv0, acc[mt][nt][1] + bv0);
            *(float2*)(Yb + (size_t)(row + 8) * N_ + col) = make_float2(acc[mt][nt][2] + bv1, acc[mt][nt][3] + bv1);
        }
}

// ---------------------------------------------------------------------------
// Transpose [C_][N_] -> [N_][C_] per batch. grid (32,16,B_), block (32,8)
// ---------------------------------------------------------------------------
__global__ void k_tr(const float* __restrict__ in, float* __restrict__ out) {
    __shared__ float tile[32][33];
    int b = blockIdx.z;
    const float* ib = in + (size_t)b * C_ * N_;
    float*       ob = out + (size_t)b * N_ * C_;
    int n0 = blockIdx.x * 32, c0 = blockIdx.y * 32;
    int tx = threadIdx.x, ty = threadIdx.y;
#pragma unroll
    for (int j = 0; j < 4; ++j)
        tile[ty + 8 * j][tx] = ib[(size_t)(c0 + ty + 8 * j) * N_ + n0 + tx];
    __syncthreads();
#pragma unroll
    for (int j = 0; j < 4; ++j)
        ob[(size_t)(n0 + ty + 8 * j) * C_ + c0 + tx] = tile[tx][ty + 8 * j];
}

// ---------------------------------------------------------------------------
// Prep + elementwise kernels
// ---------------------------------------------------------------------------
__global__ void k_wt(const float* __restrict__ w, float* __restrict__ wt) {
    size_t i = (size_t)blockIdx.x * 256 + threadIdx.x;
    if (i >= WTSZ) return;
    int ci  = (int)(i % (2 * C_));
    int co  = (int)((i / (2 * C_)) % C_);
    int tap = (int)(i / ((size_t)C_ * 2 * C_));
    wt[i] = w[((size_t)co * (2 * C_) + ci) * 9 + tap];
}

__global__ void k_wru(const float* __restrict__ wr, const float* __restrict__ wu,
                      float* __restrict__ wru) {
    size_t i = (size_t)blockIdx.x * 256 + threadIdx.x;
    size_t half = (size_t)C_ * 2 * C_;
    if (i < half) wru[i] = wr[i];
    else if (i < 2 * half) wru[i] = wu[i - half];
}

__global__ void k_init(const float* __restrict__ a, const float* __restrict__ b,
                       const float* __restrict__ c) {
    size_t i = ((size_t)blockIdx.x * 256 + threadIdx.x) * 4;
    *(float4*)(g_ex + i) = *(const float4*)(a + i);
    *(float4*)(g_q  + i) = *(const float4*)(b + i);
    *(float4*)(g_q1 + i) = *(const float4*)(c + i);
}

__global__ void k_gruout(float* __restrict__ h, const float* __restrict__ u,
                         const float* __restrict__ c) {
    size_t i = ((size_t)blockIdx.x * 256 + threadIdx.x) * 4;
    float4 hv = *(float4*)(h + i);
    float4 uv = *(const float4*)(u + i);
    float4 cv = *(const float4*)(c + i);
    hv.x = hv.x * (1.f - uv.x) + cv.x * uv.x;
    hv.y = hv.y * (1.f - uv.y) + cv.y * uv.y;
    hv.z = hv.z * (1.f - uv.z) + cv.z * uv.z;
    hv.w = hv.w * (1.f - uv.w) + cv.w * uv.w;
    *(float4*)(h + i) = hv;
}

// ---------------------------------------------------------------------------
// Host orchestration
// ---------------------------------------------------------------------------
extern "C" void kernel_launch(void* const* d_in, const int* in_sizes, int n_in,
                              void* d_out, int out_size) {
    const float* in1      = (const float*)d_in[0];
    const float* in2      = (const float*)d_in[1];
    const float* in3      = (const float*)d_in[2];
    const float* w_fusion = (const float*)d_in[3];
    const float* b_fusion = (const float*)d_in[4];
    const float* w_out    = (const float*)d_in[5];
    const float* b_out    = (const float*)d_in[6];
    const float* w_reset  = (const float*)d_in[7];
    const float* b_reset  = (const float*)d_in[8];
    const float* w_update = (const float*)d_in[9];
    const float* b_update = (const float*)d_in[10];
    const float* w_cand   = (const float*)d_in[11];
    const float* b_cand   = (const float*)d_in[12];
    float* out = (float*)d_out;

    float *S, *O1, *O2, *a1, *a2, *a3, *ex, *q, *q1, *r, *u, *c;
    float *exT, *qT, *q1T, *a1T, *a2T, *a3T, *wf, *wo, *wru;
    cudaGetSymbolAddress((void**)&S,   g_S);
    cudaGetSymbolAddress((void**)&O1,  g_O1);
    cudaGetSymbolAddress((void**)&O2,  g_O2);
    cudaGetSymbolAddress((void**)&a1,  g_a1);
    cudaGetSymbolAddress((void**)&a2,  g_a2);
    cudaGetSymbolAddress((void**)&a3,  g_a3);
    cudaGetSymbolAddress((void**)&ex,  g_ex);
    cudaGetSymbolAddress((void**)&q,   g_q);
    cudaGetSymbolAddress((void**)&q1,  g_q1);
    cudaGetSymbolAddress((void**)&r,   g_r);
    cudaGetSymbolAddress((void**)&u,   g_u);
    cudaGetSymbolAddress((void**)&c,   g_c);
    cudaGetSymbolAddress((void**)&exT, g_exT);
    cudaGetSymbolAddress((void**)&qT,  g_qT);
    cudaGetSymbolAddress((void**)&q1T, g_q1T);
    cudaGetSymbolAddress((void**)&a1T, g_a1T);
    cudaGetSymbolAddress((void**)&a2T, g_a2T);
    cudaGetSymbolAddress((void**)&a3T, g_a3T);
    cudaGetSymbolAddress((void**)&wf,  g_wf);
    cudaGetSymbolAddress((void**)&wo,  g_wo);
    cudaGetSymbolAddress((void**)&wru, g_wru);

    const int EWG = (int)(TSZ / 4 / 256);
    const int WTG = (int)((WTSZ + 255) / 256);
    const int RUG = (int)(((size_t)2 * C_ * 2 * C_ + 255) / 256);

    k_init<<<EWG, 256>>>(in1, in2, in3);
    k_wt<<<WTG, 256>>>(w_fusion, wf);
    k_wt<<<WTG, 256>>>(w_out, wo);
    k_wru<<<RUG, 256>>>(w_reset, w_update, wru);

    dim3 trG(32, 16, B_), trB(32, 8);
    dim3 gSC(8, 8, B_);     // scores: 128x128 tiles over [n,m]
    dim3 gAT(8, 4, B_);     // attmm/conv/cand
    dim3 gRU(8, 8, B_);     // fused RU (M=1024)

    for (int round = 0; round < 5; ++round) {
        k_tr<<<trG, trB>>>(ex, exT);
        k_tr<<<trG, trB>>>(q,  qT);
        k_tr<<<trG, trB>>>(q1, q1T);

        // a1 = conv(att(ex,q) || att(ex,q1))
        k_scores<<<gSC, 128>>>(exT, qT, S);
        k_softmax<<<B_ * N_, 256>>>(S);
        k_attmm<<<gAT, 128>>>(q, S, O1);
        k_scores<<<gSC, 128>>>(exT, q1T, S);
        k_softmax<<<B_ * N_, 256>>>(S);
        k_attmm<<<gAT, 128>>>(q1, S, O2);
        k_conv3<<<gAT, 128>>>(wf, O1, O2, b_fusion, a1);

        // a2 = conv(att(q,ex) || att(q,q1))
        k_scores<<<gSC, 128>>>(qT, exT, S);
        k_softmax<<<B_ * N_, 256>>>(S);
        k_attmm<<<gAT, 128>>>(ex, S, O1);
        k_scores<<<gSC, 128>>>(qT, q1T, S);
        k_softmax<<<B_ * N_, 256>>>(S);
        k_attmm<<<gAT, 128>>>(q1, S, O2);
        k_conv3<<<gAT, 128>>>(wf, O1, O2, b_fusion, a2);

        // a3 = conv(att(q1,ex) || att(q1,q))
        k_scores<<<gSC, 128>>>(q1T, exT, S);
        k_softmax<<<B_ * N_, 256>>>(S);
        k_attmm<<<gAT, 128>>>(ex, S, O1);
        k_scores<<<gSC, 128>>>(q1T, qT, S);
        k_softmax<<<B_ * N_, 256>>>(S);
        k_attmm<<<gAT, 128>>>(q, S, O2);
        k_conv3<<<gAT, 128>>>(wf, O1, O2, b_fusion, a3);

        k_tr<<<trG, trB>>>(a1, a1T);
        k_tr<<<trG, trB>>>(a2, a2T);
        k_tr<<<trG, trB>>>(a3, a3T);

        float* xTs[3] = {a1T, a2T, a3T};
        float* hTs[3] = {exT, qT, q1T};
        float* hs [3] = {ex,  q,  q1};
        for (int s = 0; s < 3; ++s) {
            k_gemmRU<<<gRU, 128>>>(wru, xTs[s], hTs[s], b_reset, b_update, r, u);
            k_gemmCAND<<<gAT, 128>>>(w_cand, xTs[s], r, hs[s], b_cand, c);
            k_gruout<<<EWG, 256>>>(hs[s], u, c);
        }
    }

    k_conv3<<<gAT, 128>>>(wo, ex, in1, b_out, out);
    k_conv3<<<gAT, 128>>>(wo, q,  in2, b_out, out + TSZ);
    k_conv3<<<gAT, 128>>>(wo, q1, in3, b_out, out + 2 * TSZ);
}

// round 6
// speedup vs baseline: 3.3048x; 1.0221x over previous
#include <cuda_runtime.h>
#include <cuda_fp16.h>
#include <math.h>
#include <stdint.h>

// ---------------------------------------------------------------------------
// Problem constants
// ---------------------------------------------------------------------------
#define B_  16
#define C_  512
#define N_  1024
#define HW  32
#define SPITCH 12   // smem row stride in u32 (8 used + 4 pad): conflict-free

static constexpr size_t TSZ  = (size_t)B_ * C_ * N_;
static constexpr size_t WTSZ = (size_t)9 * C_ * (2 * C_);

// ---------------------------------------------------------------------------
// Scratch (static device globals; no allocation anywhere)
// ---------------------------------------------------------------------------
__device__ float g_S [(size_t)B_ * N_ * N_];
__device__ float g_O1[TSZ], g_O2[TSZ];
__device__ float g_a1[TSZ], g_a2[TSZ], g_a3[TSZ];
__device__ float g_ex[TSZ], g_q [TSZ], g_q1[TSZ];
__device__ float g_r [TSZ], g_u [TSZ], g_c [TSZ];
__device__ float g_exT[TSZ], g_qT[TSZ], g_q1T[TSZ];      // [b][n][c]
__device__ float g_a1T[TSZ], g_a2T[TSZ], g_a3T[TSZ];     // [b][p][co]
__device__ float g_wf[WTSZ], g_wo[WTSZ];                 // [tap][co][ci]
__device__ float g_wru[(size_t)2 * C_ * 2 * C_];         // concat reset|update

// ---------------------------------------------------------------------------
// fp16 mma.sync microkernel: 4 warps, warp tile 64x64, block tile 128x128
// smem: half2-packed operands, layout [row][kpair], stride SPITCH u32.
// Fragment loads via ldmatrix.x4 (8 LDSM per slab instead of 32 LDS.32).
// ---------------------------------------------------------------------------
__device__ __forceinline__ uint32_t h2(float lo, float hi) {
    __half2 h = __floats2half2_rn(lo, hi);
    return *(uint32_t*)&h;
}

__device__ __forceinline__ void mma16(float* d, const uint32_t* a, uint32_t b0, uint32_t b1) {
    asm volatile(
        "mma.sync.aligned.m16n8k16.row.col.f32.f16.f16.f32 "
        "{%0,%1,%2,%3}, {%4,%5,%6,%7}, {%8,%9}, {%0,%1,%2,%3};\n"
        : "+f"(d[0]), "+f"(d[1]), "+f"(d[2]), "+f"(d[3])
        : "r"(a[0]), "r"(a[1]), "r"(a[2]), "r"(a[3]), "r"(b0), "r"(b1));
}

__device__ __forceinline__ void ldsm4(uint32_t* r, uint32_t addr) {
    asm volatile(
        "ldmatrix.sync.aligned.m8n8.x4.shared.b16 {%0,%1,%2,%3}, [%4];"
        : "=r"(r[0]), "=r"(r[1]), "=r"(r[2]), "=r"(r[3]) : "r"(addr));
}

// One K=16 slab, warp tile 64x64.
// aB/bB: shared-space byte addresses of the slab's A/B tile bases.
// Lane address map for ldmatrix.x4 over a 16-row x 16-col fp16 tile:
//   row = tile_row0 + (lane&15), byte col = (lane>>4)*16.
__device__ __forceinline__ void compute16(uint32_t aB, uint32_t bB,
                                          float (*acc)[8][4], int wm, int wn,
                                          int lane) {
    int lr = lane & 15;
    uint32_t lc = (uint32_t)(lane >> 4) * 16;
    uint32_t a[4][4], b[4][4];
#pragma unroll
    for (int mt = 0; mt < 4; ++mt)
        ldsm4(a[mt], aB + (uint32_t)(wm + mt * 16 + lr) * (SPITCH * 4) + lc);
#pragma unroll
    for (int np = 0; np < 4; ++np)
        ldsm4(b[np], bB + (uint32_t)(wn + np * 16 + lr) * (SPITCH * 4) + lc);
    // b[np] regs: r0 = nt=2np k0-7, r1 = nt=2np+1 k0-7, r2 = nt=2np k8-15, r3 = nt=2np+1 k8-15
#pragma unroll
    for (int mt = 0; mt < 4; ++mt)
#pragma unroll
        for (int np = 0; np < 4; ++np) {
            mma16(acc[mt][2 * np],     a[mt], b[np][0], b[np][2]);
            mma16(acc[mt][2 * np + 1], a[mt], b[np][1], b[np][3]);
        }
}

#define ZERO_ACC(acc)                                       \
    float acc[4][8][4];                                     \
    _Pragma("unroll")                                       \
    for (int i_ = 0; i_ < 4; ++i_)                          \
        _Pragma("unroll")                                   \
        for (int j_ = 0; j_ < 8; ++j_)                      \
            _Pragma("unroll")                               \
            for (int v_ = 0; v_ < 4; ++v_) acc[i_][j_][v_] = 0.f;

#define WARP_COORDS()                                                        \
    int t = threadIdx.x, lane = t & 31, wid = t >> 5;                        \
    int wm = (wid & 1) * 64, wn = (wid >> 1) * 64;                           \
    int g = lane >> 2, tg = lane & 3;                                        \
    uint32_t sAs = (uint32_t)__cvta_generic_to_shared(&As[0][0][0]);         \
    uint32_t sBs = (uint32_t)__cvta_generic_to_shared(&Bs[0][0][0]);         \
    const uint32_t bufStride = 128 * SPITCH * 4;                             \
    (void)g; (void)tg;

// Staging register buffer: 16 fp32 values = one smem row (one thread per row)
struct Stage { float v[16]; };

__device__ __forceinline__ void ld_contig(Stage& s, const float* __restrict__ p) {
#pragma unroll
    for (int i = 0; i < 4; ++i) {
        float4 f = *(const float4*)(p + 4 * i);
        s.v[4 * i] = f.x; s.v[4 * i + 1] = f.y; s.v[4 * i + 2] = f.z; s.v[4 * i + 3] = f.w;
    }
}

__device__ __forceinline__ void st_row(const Stage& s, uint32_t (*M)[SPITCH], int row) {
    uint4 w0 = make_uint4(h2(s.v[0], s.v[1]),  h2(s.v[2], s.v[3]),
                          h2(s.v[4], s.v[5]),  h2(s.v[6], s.v[7]));
    uint4 w1 = make_uint4(h2(s.v[8], s.v[9]),  h2(s.v[10], s.v[11]),
                          h2(s.v[12], s.v[13]), h2(s.v[14], s.v[15]));
    *(uint4*)&M[row][0] = w0;
    *(uint4*)&M[row][4] = w1;
}

// ---------------------------------------------------------------------------
// k_scores: S[b,n,m] = sum_c ET[n,c] * QT[m,c].  grid (8,8,16), 128 thr
// ---------------------------------------------------------------------------
__global__ void __launch_bounds__(128, 2) k_scores(const float* __restrict__ ET,
                                                   const float* __restrict__ QT,
                                                   float* __restrict__ S) {
    int b = blockIdx.z;
    const float* At = ET + (size_t)b * N_ * C_;
    const float* Bt = QT + (size_t)b * N_ * C_;
    float*       Sb = S  + (size_t)b * N_ * N_;
    int n0 = blockIdx.y * 128, m0 = blockIdx.x * 128;

    __shared__ uint32_t As[2][128][SPITCH], Bs[2][128][SPITCH];
    WARP_COORDS();

    Stage sa, sb;
    ld_contig(sa, At + (size_t)(n0 + t) * C_);
    ld_contig(sb, Bt + (size_t)(m0 + t) * C_);
    st_row(sa, As[0], t); st_row(sb, Bs[0], t);
    __syncthreads();

    ZERO_ACC(acc);
    const int KI = C_ / 16;   // 32
    for (int it = 0; it < KI; ++it) {
        int nx = it + 1;
        if (nx < KI) {
            ld_contig(sa, At + (size_t)(n0 + t) * C_ + nx * 16);
            ld_contig(sb, Bt + (size_t)(m0 + t) * C_ + nx * 16);
        }
        compute16(sAs + (it & 1) * bufStride, sBs + (it & 1) * bufStride, acc, wm, wn, lane);
        if (nx < KI) { st_row(sa, As[nx & 1], t); st_row(sb, Bs[nx & 1], t); }
        __syncthreads();
    }

#pragma unroll
    for (int mt = 0; mt < 4; ++mt)
#pragma unroll
        for (int nt = 0; nt < 8; ++nt) {
            int row = n0 + wm + mt * 16 + g;
            int col = m0 + wn + nt * 8 + tg * 2;
            *(float2*)(Sb + (size_t)row * N_ + col)       = make_float2(acc[mt][nt][0], acc[mt][nt][1]);
            *(float2*)(Sb + (size_t)(row + 8) * N_ + col) = make_float2(acc[mt][nt][2], acc[mt][nt][3]);
        }
}

// ---------------------------------------------------------------------------
// Row softmax over m. grid = B_*N_, 256 threads
// ---------------------------------------------------------------------------
__global__ void __launch_bounds__(256) k_softmax(float* __restrict__ S) {
    float* row = S + (size_t)blockIdx.x * N_;
    int t = threadIdx.x;
    float4 v = *(float4*)(row + 4 * t);
    __shared__ float red[8];

    float m = fmaxf(fmaxf(v.x, v.y), fmaxf(v.z, v.w));
#pragma unroll
    for (int o = 16; o; o >>= 1) m = fmaxf(m, __shfl_xor_sync(0xffffffffu, m, o));
    if ((t & 31) == 0) red[t >> 5] = m;
    __syncthreads();
    float mx = red[0];
#pragma unroll
    for (int i = 1; i < 8; ++i) mx = fmaxf(mx, red[i]);
    __syncthreads();

    v.x = __expf(v.x - mx); v.y = __expf(v.y - mx);
    v.z = __expf(v.z - mx); v.w = __expf(v.w - mx);
    float s = v.x + v.y + v.z + v.w;
#pragma unroll
    for (int o = 16; o; o >>= 1) s += __shfl_xor_sync(0xffffffffu, s, o);
    if ((t & 31) == 0) red[t >> 5] = s;
    __syncthreads();
    float tot = red[0];
#pragma unroll
    for (int i = 1; i < 8; ++i) tot += red[i];
    float inv = 1.f / tot;
    v.x *= inv; v.y *= inv; v.z *= inv; v.w *= inv;
    *(float4*)(row + 4 * t) = v;
}

// ---------------------------------------------------------------------------
// k_attmm: O[b,c,n] = sum_m Q[c,m] * S[n,m].  grid (8,4,16), 128 thr
// ---------------------------------------------------------------------------
__global__ void __launch_bounds__(128, 2) k_attmm(const float* __restrict__ Q,
                                                  const float* __restrict__ S,
                                                  float* __restrict__ O) {
    int b = blockIdx.z;
    const float* Qb = Q + (size_t)b * C_ * N_;
    const float* Sb = S + (size_t)b * N_ * N_;
    float*       Ob = O + (size_t)b * C_ * N_;
    int c0 = blockIdx.y * 128, n0 = blockIdx.x * 128;

    __shared__ uint32_t As[2][128][SPITCH], Bs[2][128][SPITCH];
    WARP_COORDS();

    Stage sa, sb;
    ld_contig(sa, Qb + (size_t)(c0 + t) * N_);
    ld_contig(sb, Sb + (size_t)(n0 + t) * N_);
    st_row(sa, As[0], t); st_row(sb, Bs[0], t);
    __syncthreads();

    ZERO_ACC(acc);
    const int KI = N_ / 16;   // 64
    for (int it = 0; it < KI; ++it) {
        int nx = it + 1;
        if (nx < KI) {
            ld_contig(sa, Qb + (size_t)(c0 + t) * N_ + nx * 16);
            ld_contig(sb, Sb + (size_t)(n0 + t) * N_ + nx * 16);
        }
        compute16(sAs + (it & 1) * bufStride, sBs + (it & 1) * bufStride, acc, wm, wn, lane);
        if (nx < KI) { st_row(sa, As[nx & 1], t); st_row(sb, Bs[nx & 1], t); }
        __syncthreads();
    }

#pragma unroll
    for (int mt = 0; mt < 4; ++mt)
#pragma unroll
        for (int nt = 0; nt < 8; ++nt) {
            int row = c0 + wm + mt * 16 + g;
            int col = n0 + wn + nt * 8 + tg * 2;
            *(float2*)(Ob + (size_t)row * N_ + col)       = make_float2(acc[mt][nt][0], acc[mt][nt][1]);
            *(float2*)(Ob + (size_t)(row + 8) * N_ + col) = make_float2(acc[mt][nt][2], acc[mt][nt][3]);
        }
}

// ---------------------------------------------------------------------------
// k_gemmRU: fused reset+update. M=1024 (rows 0-511 -> r, 512-1023 -> u),
// K=1024 with B = [x(aT) ; h(hT)], both contiguous. grid (8,8,16)
// ---------------------------------------------------------------------------
__global__ void __launch_bounds__(128, 2) k_gemmRU(const float* __restrict__ Wru,
                                                   const float* __restrict__ xT,
                                                   const float* __restrict__ hT,
                                                   const float* __restrict__ b_r,
                                                   const float* __restrict__ b_u,
                                                   float* __restrict__ R,
                                                   float* __restrict__ U) {
    int b = blockIdx.z;
    const float* xTb = xT + (size_t)b * N_ * C_;
    const float* hTb = hT + (size_t)b * N_ * C_;
    int co0 = blockIdx.y * 128, p0 = blockIdx.x * 128;

    __shared__ uint32_t As[2][128][SPITCH], Bs[2][128][SPITCH];
    WARP_COORDS();

    Stage sa, sb;
    auto ldB = [&](int ci0) {
        const float* src = (ci0 < C_) ? (xTb + (size_t)(p0 + t) * C_ + ci0)
                                      : (hTb + (size_t)(p0 + t) * C_ + (ci0 - C_));
        ld_contig(sb, src);
    };
    ld_contig(sa, Wru + (size_t)(co0 + t) * (2 * C_));
    ldB(0);
    st_row(sa, As[0], t); st_row(sb, Bs[0], t);
    __syncthreads();

    ZERO_ACC(acc);
    const int KI = (2 * C_) / 16;   // 64
    for (int it = 0; it < KI; ++it) {
        int nx = it + 1;
        if (nx < KI) {
            ld_contig(sa, Wru + (size_t)(co0 + t) * (2 * C_) + nx * 16);
            ldB(nx * 16);
        }
        compute16(sAs + (it & 1) * bufStride, sBs + (it & 1) * bufStride, acc, wm, wn, lane);
        if (nx < KI) { st_row(sa, As[nx & 1], t); st_row(sb, Bs[nx & 1], t); }
        __syncthreads();
    }

    bool isR = co0 < C_;
    float* dst = (isR ? R : U) + (size_t)b * C_ * N_;
    int rbase = isR ? co0 : (co0 - C_);
    const float* bias = isR ? b_r : b_u;
#pragma unroll
    for (int mt = 0; mt < 4; ++mt)
#pragma unroll
        for (int nt = 0; nt < 8; ++nt) {
            int row = rbase + wm + mt * 16 + g;
            int col = p0 + wn + nt * 8 + tg * 2;
            float bv0 = bias[row], bv1 = bias[row + 8];
            float o0 = 1.f / (1.f + __expf(-(acc[mt][nt][0] + bv0)));
            float o1 = 1.f / (1.f + __expf(-(acc[mt][nt][1] + bv0)));
            float o2 = 1.f / (1.f + __expf(-(acc[mt][nt][2] + bv1)));
            float o3 = 1.f / (1.f + __expf(-(acc[mt][nt][3] + bv1)));
            *(float2*)(dst + (size_t)row * N_ + col)       = make_float2(o0, o1);
            *(float2*)(dst + (size_t)(row + 8) * N_ + col) = make_float2(o2, o3);
        }
}

// ---------------------------------------------------------------------------
// k_gemmCAND: c = tanh(Wc @ [x ; r*h] + b).  grid (8,4,16)
// ---------------------------------------------------------------------------
__global__ void __launch_bounds__(128, 2) k_gemmCAND(const float* __restrict__ Wc,
                                                     const float* __restrict__ xT,
                                                     const float* __restrict__ R,
                                                     const float* __restrict__ H,
                                                     const float* __restrict__ bias,
                                                     float* __restrict__ Y) {
    int b = blockIdx.z;
    const float* xTb = xT + (size_t)b * N_ * C_;
    const float* Rb  = R  + (size_t)b * C_ * N_;
    const float* Hb  = H  + (size_t)b * C_ * N_;
    float*       Yb  = Y  + (size_t)b * C_ * N_;
    int co0 = blockIdx.y * 128, p0 = blockIdx.x * 128;

    __shared__ uint32_t As[2][128][SPITCH], Bs[2][128][SPITCH];
    WARP_COORDS();

    Stage sa, sb;
    auto ldB = [&](int ci0) {
        if (ci0 < C_) {
            ld_contig(sb, xTb + (size_t)(p0 + t) * C_ + ci0);
        } else {
            int ch = ci0 - C_;
            const float* rp = Rb + (size_t)ch * N_ + p0 + t;
            const float* hp = Hb + (size_t)ch * N_ + p0 + t;
#pragma unroll
            for (int k = 0; k < 16; ++k)
                sb.v[k] = rp[(size_t)k * N_] * hp[(size_t)k * N_];
        }
    };
    ld_contig(sa, Wc + (size_t)(co0 + t) * (2 * C_));
    ldB(0);
    st_row(sa, As[0], t); st_row(sb, Bs[0], t);
    __syncthreads();

    ZERO_ACC(acc);
    const int KI = (2 * C_) / 16;
    for (int it = 0; it < KI; ++it) {
        int nx = it + 1;
        if (nx < KI) {
            ld_contig(sa, Wc + (size_t)(co0 + t) * (2 * C_) + nx * 16);
            ldB(nx * 16);
        }
        compute16(sAs + (it & 1) * bufStride, sBs + (it & 1) * bufStride, acc, wm, wn, lane);
        if (nx < KI) { st_row(sa, As[nx & 1], t); st_row(sb, Bs[nx & 1], t); }
        __syncthreads();
    }

#pragma unroll
    for (int mt = 0; mt < 4; ++mt)
#pragma unroll
        for (int nt = 0; nt < 8; ++nt) {
            int row = co0 + wm + mt * 16 + g;
            int col = p0 + wn + nt * 8 + tg * 2;
            float bv0 = bias[row], bv1 = bias[row + 8];
            *(float2*)(Yb + (size_t)row * N_ + col) =
                make_float2(tanhf(acc[mt][nt][0] + bv0), tanhf(acc[mt][nt][1] + bv0));
            *(float2*)(Yb + (size_t)(row + 8) * N_ + col) =
                make_float2(tanhf(acc[mt][nt][2] + bv1), tanhf(acc[mt][nt][3] + bv1));
        }
}

// ---------------------------------------------------------------------------
// k_conv3: 3x3 conv pad 1, implicit GEMM K=9*1024.  grid (8,4,16), 128 thr
// ---------------------------------------------------------------------------
__global__ void __launch_bounds__(128, 2) k_conv3(const float* __restrict__ Wt,
                                                  const float* __restrict__ X0,
                                                  const float* __restrict__ X1,
                                                  const float* __restrict__ bias,
                                                  float* __restrict__ Y) {
    int b = blockIdx.z;
    const float* x0 = X0 + (size_t)b * C_ * N_;
    const float* x1 = X1 + (size_t)b * C_ * N_;
    float*       Yb = Y  + (size_t)b * C_ * N_;
    int co0 = blockIdx.y * 128, p0 = blockIdx.x * 128;

    __shared__ uint32_t As[2][128][SPITCH], Bs[2][128][SPITCH];
    WARP_COORDS();

    int p = p0 + t;
    int py = p >> 5, px = p & 31;

    Stage sa, sb;
    auto ldA = [&](int it) {
        int tap = it >> 6, ci0 = (it & 63) * 16;
        ld_contig(sa, Wt + (size_t)tap * C_ * (2 * C_)
                         + (size_t)(co0 + t) * (2 * C_) + ci0);
    };
    auto ldB = [&](int it) {
        int tap = it >> 6, ci0 = (it & 63) * 16;
        int dy = tap / 3 - 1, dx = tap % 3 - 1;
        int y = py + dy, x = px + dx;
        bool ok = ((unsigned)y < HW) && ((unsigned)x < HW);
        const float* src = (ci0 < C_) ? (x0 + (size_t)ci0 * N_)
                                      : (x1 + (size_t)(ci0 - C_) * N_);
        const float* pp = src + y * HW + x;
#pragma unroll
        for (int k = 0; k < 16; ++k)
            sb.v[k] = ok ? pp[(size_t)k * N_] : 0.f;
    };

    ldA(0); ldB(0);
    st_row(sa, As[0], t); st_row(sb, Bs[0], t);
    __syncthreads();

    ZERO_ACC(acc);
    const int KI = 9 * (2 * C_) / 16;   // 576
    for (int it = 0; it < KI; ++it) {
        int nx = it + 1;
        if (nx < KI) { ldA(nx); ldB(nx); }
        compute16(sAs + (it & 1) * bufStride, sBs + (it & 1) * bufStride, acc, wm, wn, lane);
        if (nx < KI) { st_row(sa, As[nx & 1], t); st_row(sb, Bs[nx & 1], t); }
        __syncthreads();
    }

#pragma unroll
    for (int mt = 0; mt < 4; ++mt)
#pragma unroll
        for (int nt = 0; nt < 8; ++nt) {
            int row = co0 + wm + mt * 16 + g;
            int col = p0 + wn + nt * 8 + tg * 2;
            float bv0 = bias[row], bv1 = bias[row + 8];
            *(float2*)(Yb + (size_t)row * N_ + col)       = make_float2(acc[mt][nt][0] + bv0, acc[mt][nt][1] + bv0);
            *(float2*)(Yb + (size_t)(row + 8) * N_ + col) = make_float2(acc[mt][nt][2] + bv1, acc[mt][nt][3] + bv1);
        }
}

// ---------------------------------------------------------------------------
// Transpose [C_][N_] -> [N_][C_] per batch. grid (32,16,B_), block (32,8)
// ---------------------------------------------------------------------------
__global__ void k_tr(const float* __restrict__ in, float* __restrict__ out) {
    __shared__ float tile[32][33];
    int b = blockIdx.z;
    const float* ib = in + (size_t)b * C_ * N_;
    float*       ob = out + (size_t)b * N_ * C_;
    int n0 = blockIdx.x * 32, c0 = blockIdx.y * 32;
    int tx = threadIdx.x, ty = threadIdx.y;
#pragma unroll
    for (int j = 0; j < 4; ++j)
        tile[ty + 8 * j][tx] = ib[(size_t)(c0 + ty + 8 * j) * N_ + n0 + tx];
    __syncthreads();
#pragma unroll
    for (int j = 0; j < 4; ++j)
        ob[(size_t)(n0 + ty + 8 * j) * C_ + c0 + tx] = tile[tx][ty + 8 * j];
}

// ---------------------------------------------------------------------------
// Prep + elementwise kernels
// ---------------------------------------------------------------------------
__global__ void k_wt(const float* __restrict__ w, float* __restrict__ wt) {
    size_t i = (size_t)blockIdx.x * 256 + threadIdx.x;
    if (i >= WTSZ) return;
    int ci  = (int)(i % (2 * C_));
    int co  = (int)((i / (2 * C_)) % C_);
    int tap = (int)(i / ((size_t)C_ * 2 * C_));
    wt[i] = w[((size_t)co * (2 * C_) + ci) * 9 + tap];
}

__global__ void k_wru(const float* __restrict__ wr, const float* __restrict__ wu,
                      float* __restrict__ wru) {
    size_t i = (size_t)blockIdx.x * 256 + threadIdx.x;
    size_t half = (size_t)C_ * 2 * C_;
    if (i < half) wru[i] = wr[i];
    else if (i < 2 * half) wru[i] = wu[i - half];
}

__global__ void k_init(const float* __restrict__ a, const float* __restrict__ b,
                       const float* __restrict__ c) {
    size_t i = ((size_t)blockIdx.x * 256 + threadIdx.x) * 4;
    *(float4*)(g_ex + i) = *(const float4*)(a + i);
    *(float4*)(g_q  + i) = *(const float4*)(b + i);
    *(float4*)(g_q1 + i) = *(const float4*)(c + i);
}

__global__ void k_gruout(float* __restrict__ h, const float* __restrict__ u,
                         const float* __restrict__ c) {
    size_t i = ((size_t)blockIdx.x * 256 + threadIdx.x) * 4;
    float4 hv = *(float4*)(h + i);
    float4 uv = *(const float4*)(u + i);
    float4 cv = *(const float4*)(c + i);
    hv.x = hv.x * (1.f - uv.x) + cv.x * uv.x;
    hv.y = hv.y * (1.f - uv.y) + cv.y * uv.y;
    hv.z = hv.z * (1.f - uv.z) + cv.z * uv.z;
    hv.w = hv.w * (1.f - uv.w) + cv.w * uv.w;
    *(float4*)(h + i) = hv;
}

// ---------------------------------------------------------------------------
// Host orchestration
// ---------------------------------------------------------------------------
extern "C" void kernel_launch(void* const* d_in, const int* in_sizes, int n_in,
                              void* d_out, int out_size) {
    const float* in1      = (const float*)d_in[0];
    const float* in2      = (const float*)d_in[1];
    const float* in3      = (const float*)d_in[2];
    const float* w_fusion = (const float*)d_in[3];
    const float* b_fusion = (const float*)d_in[4];
    const float* w_out    = (const float*)d_in[5];
    const float* b_out    = (const float*)d_in[6];
    const float* w_reset  = (const float*)d_in[7];
    const float* b_reset  = (const float*)d_in[8];
    const float* w_update = (const float*)d_in[9];
    const float* b_update = (const float*)d_in[10];
    const float* w_cand   = (const float*)d_in[11];
    const float* b_cand   = (const float*)d_in[12];
    float* out = (float*)d_out;

    float *S, *O1, *O2, *a1, *a2, *a3, *ex, *q, *q1, *r, *u, *c;
    float *exT, *qT, *q1T, *a1T, *a2T, *a3T, *wf, *wo, *wru;
    cudaGetSymbolAddress((void**)&S,   g_S);
    cudaGetSymbolAddress((void**)&O1,  g_O1);
    cudaGetSymbolAddress((void**)&O2,  g_O2);
    cudaGetSymbolAddress((void**)&a1,  g_a1);
    cudaGetSymbolAddress((void**)&a2,  g_a2);
    cudaGetSymbolAddress((void**)&a3,  g_a3);
    cudaGetSymbolAddress((void**)&ex,  g_ex);
    cudaGetSymbolAddress((void**)&q,   g_q);
    cudaGetSymbolAddress((void**)&q1,  g_q1);
    cudaGetSymbolAddress((void**)&r,   g_r);
    cudaGetSymbolAddress((void**)&u,   g_u);
    cudaGetSymbolAddress((void**)&c,   g_c);
    cudaGetSymbolAddress((void**)&exT, g_exT);
    cudaGetSymbolAddress((void**)&qT,  g_qT);
    cudaGetSymbolAddress((void**)&q1T, g_q1T);
    cudaGetSymbolAddress((void**)&a1T, g_a1T);
    cudaGetSymbolAddress((void**)&a2T, g_a2T);
    cudaGetSymbolAddress((void**)&a3T, g_a3T);
    cudaGetSymbolAddress((void**)&wf,  g_wf);
    cudaGetSymbolAddress((void**)&wo,  g_wo);
    cudaGetSymbolAddress((void**)&wru, g_wru);

    const int EWG = (int)(TSZ / 4 / 256);
    const int WTG = (int)((WTSZ + 255) / 256);
    const int RUG = (int)(((size_t)2 * C_ * 2 * C_ + 255) / 256);

    k_init<<<EWG, 256>>>(in1, in2, in3);
    k_wt<<<WTG, 256>>>(w_fusion, wf);
    k_wt<<<WTG, 256>>>(w_out, wo);
    k_wru<<<RUG, 256>>>(w_reset, w_update, wru);

    dim3 trG(32, 16, B_), trB(32, 8);
    dim3 gSC(8, 8, B_);     // scores: 128x128 tiles over [n,m]
    dim3 gAT(8, 4, B_);     // attmm/conv/cand
    dim3 gRU(8, 8, B_);     // fused RU (M=1024)

    for (int round = 0; round < 5; ++round) {
        k_tr<<<trG, trB>>>(ex, exT);
        k_tr<<<trG, trB>>>(q,  qT);
        k_tr<<<trG, trB>>>(q1, q1T);

        // a1 = conv(att(ex,q) || att(ex,q1))
        k_scores<<<gSC, 128>>>(exT, qT, S);
        k_softmax<<<B_ * N_, 256>>>(S);
        k_attmm<<<gAT, 128>>>(q, S, O1);
        k_scores<<<gSC, 128>>>(exT, q1T, S);
        k_softmax<<<B_ * N_, 256>>>(S);
        k_attmm<<<gAT, 128>>>(q1, S, O2);
        k_conv3<<<gAT, 128>>>(wf, O1, O2, b_fusion, a1);

        // a2 = conv(att(q,ex) || att(q,q1))
        k_scores<<<gSC, 128>>>(qT, exT, S);
        k_softmax<<<B_ * N_, 256>>>(S);
        k_attmm<<<gAT, 128>>>(ex, S, O1);
        k_scores<<<gSC, 128>>>(qT, q1T, S);
        k_softmax<<<B_ * N_, 256>>>(S);
        k_attmm<<<gAT, 128>>>(q1, S, O2);
        k_conv3<<<gAT, 128>>>(wf, O1, O2, b_fusion, a2);

        // a3 = conv(att(q1,ex) || att(q1,q))
        k_scores<<<gSC, 128>>>(q1T, exT, S);
        k_softmax<<<B_ * N_, 256>>>(S);
        k_attmm<<<gAT, 128>>>(ex, S, O1);
        k_scores<<<gSC, 128>>>(q1T, qT, S);
        k_softmax<<<B_ * N_, 256>>>(S);
        k_attmm<<<gAT, 128>>>(q, S, O2);
        k_conv3<<<gAT, 128>>>(wf, O1, O2, b_fusion, a3);

        k_tr<<<trG, trB>>>(a1, a1T);
        k_tr<<<trG, trB>>>(a2, a2T);
        k_tr<<<trG, trB>>>(a3, a3T);

        float* xTs[3] = {a1T, a2T, a3T};
        float* hTs[3] = {exT, qT, q1T};
        float* hs [3] = {ex,  q,  q1};
        for (int s = 0; s < 3; ++s) {
            k_gemmRU<<<gRU, 128>>>(wru, xTs[s], hTs[s], b_reset, b_update, r, u);
            k_gemmCAND<<<gAT, 128>>>(w_cand, xTs[s], r, hs[s], b_cand, c);
            k_gruout<<<EWG, 256>>>(hs[s], u, c);
        }
    }

    k_conv3<<<gAT, 128>>>(wo, ex, in1, b_out, out);
    k_conv3<<<gAT, 128>>>(wo, q,  in2, b_out, out + TSZ);
    k_conv3<<<gAT, 128>>>(wo, q1, in3, b_out, out + 2 * TSZ);
}

// round 7
// speedup vs baseline: 4.8087x; 1.4550x over previous
#include <cuda_runtime.h>
#include <cuda_fp16.h>
#include <math.h>
#include <stdint.h>

// ---------------------------------------------------------------------------
// Problem constants
// ---------------------------------------------------------------------------
#define B_  16
#define C_  512
#define N_  1024
#define HW  32
#define SPITCH 12                      // smem row stride in u32 (48B) - conflict-free
#define NSTG 4                         // pipeline stages
#define STGSZ (128 * SPITCH * 4)       // 6144 B per matrix per stage
#define SMEM_DYN (2 * NSTG * STGSZ)    // 49152 B

static constexpr size_t TSZ  = (size_t)B_ * C_ * N_;
static constexpr size_t SSZ  = (size_t)B_ * N_ * N_;
static constexpr size_t WTSZ = (size_t)9 * C_ * (2 * C_);

// ---------------------------------------------------------------------------
// Scratch (static device globals; no allocation anywhere)
// ---------------------------------------------------------------------------
__device__ float g_S [SSZ];
__device__ float g_O1[TSZ], g_O2[TSZ], g_a[TSZ];
__device__ float g_ex[TSZ], g_q [TSZ], g_q1[TSZ];
__device__ float g_r [TSZ], g_u [TSZ], g_c [TSZ];

__device__ __align__(128) __half g_P16  [SSZ];                     // probs [n][m]
__device__ __align__(128) __half g_ex16 [TSZ], g_q16 [TSZ], g_q116[TSZ];  // [c][n]
__device__ __align__(128) __half g_exT16[TSZ], g_qT16[TSZ], g_q1T16[TSZ]; // [n][c]
__device__ __align__(128) __half g_O1T16[TSZ], g_O2T16[TSZ];       // [p][c]
__device__ __align__(128) __half g_aT16 [TSZ], g_rhT16[TSZ];       // [p][c]
__device__ __align__(128) __half g_in1T16[TSZ], g_in2T16[TSZ], g_in3T16[TSZ];
__device__ __align__(128) __half g_wf16[WTSZ], g_wo16[WTSZ];       // [tap][co][ci]
__device__ __align__(128) __half g_wru16[(size_t)(2 * C_) * (2 * C_)];
__device__ __align__(128) __half g_wc16 [(size_t)C_ * (2 * C_)];

// ---------------------------------------------------------------------------
// cp.async helpers
// ---------------------------------------------------------------------------
__device__ __forceinline__ void cpa16(uint32_t dst, const void* src, uint32_t sz) {
    asm volatile("cp.async.ca.shared.global [%0], [%1], 16, %2;"
                 :: "r"(dst), "l"(src), "r"(sz) : "memory");
}
#define CP_COMMIT() asm volatile("cp.async.commit_group;" ::: "memory")
#define CP_WAIT2()  asm volatile("cp.async.wait_group 2;" ::: "memory")

// ---------------------------------------------------------------------------
// fp16 mma.sync microkernel: 4 warps, warp tile 64x64, block tile 128x128
// ---------------------------------------------------------------------------
__device__ __forceinline__ void mma16(float* d, const uint32_t* a, uint32_t b0, uint32_t b1) {
    asm volatile(
        "mma.sync.aligned.m16n8k16.row.col.f32.f16.f16.f32 "
        "{%0,%1,%2,%3}, {%4,%5,%6,%7}, {%8,%9}, {%0,%1,%2,%3};\n"
        : "+f"(d[0]), "+f"(d[1]), "+f"(d[2]), "+f"(d[3])
        : "r"(a[0]), "r"(a[1]), "r"(a[2]), "r"(a[3]), "r"(b0), "r"(b1));
}

__device__ __forceinline__ void ldsm4(uint32_t* r, uint32_t addr) {
    asm volatile(
        "ldmatrix.sync.aligned.m8n8.x4.shared.b16 {%0,%1,%2,%3}, [%4];"
        : "=r"(r[0]), "=r"(r[1]), "=r"(r[2]), "=r"(r[3]) : "r"(addr));
}

__device__ __forceinline__ void compute16(uint32_t aB, uint32_t bB,
                                          float (*acc)[8][4], int wm, int wn,
                                          int lane) {
    int lr = lane & 15;
    uint32_t lc = (uint32_t)(lane >> 4) * 16;
    uint32_t a[4][4], b[4][4];
#pragma unroll
    for (int mt = 0; mt < 4; ++mt)
        ldsm4(a[mt], aB + (uint32_t)(wm + mt * 16 + lr) * (SPITCH * 4) + lc);
#pragma unroll
    for (int np = 0; np < 4; ++np)
        ldsm4(b[np], bB + (uint32_t)(wn + np * 16 + lr) * (SPITCH * 4) + lc);
#pragma unroll
    for (int mt = 0; mt < 4; ++mt)
#pragma unroll
        for (int np = 0; np < 4; ++np) {
            mma16(acc[mt][2 * np],     a[mt], b[np][0], b[np][2]);
            mma16(acc[mt][2 * np + 1], a[mt], b[np][1], b[np][3]);
        }
}

#define ZERO_ACC(acc)                                       \
    float acc[4][8][4];                                     \
    _Pragma("unroll")                                       \
    for (int i_ = 0; i_ < 4; ++i_)                          \
        _Pragma("unroll")                                   \
        for (int j_ = 0; j_ < 8; ++j_)                      \
            _Pragma("unroll")                               \
            for (int v_ = 0; v_ < 4; ++v_) acc[i_][j_][v_] = 0.f;

#define GEMM_PRE()                                                           \
    extern __shared__ __align__(1024) char dsm[];                            \
    int t = threadIdx.x, lane = t & 31, wid = t >> 5;                        \
    int wm = (wid & 1) * 64, wn = (wid >> 1) * 64;                           \
    int g = lane >> 2, tg = lane & 3;                                        \
    uint32_t sAs = (uint32_t)__cvta_generic_to_shared(dsm);                  \
    uint32_t sBs = sAs + NSTG * STGSZ;                                       \
    (void)g; (void)tg;

// Pipeline driver: ISSUE is a lambda(int it) issuing cp.asyncs for chunk it.
#define GEMM_PIPE(KI, ISSUE, acc)                                            \
    for (int s_ = 0; s_ < 3; ++s_) { ISSUE(s_); CP_COMMIT(); }               \
    for (int it_ = 0; it_ < (KI); ++it_) {                                   \
        CP_WAIT2();                                                          \
        __syncthreads();                                                     \
        compute16(sAs + (it_ & 3) * STGSZ, sBs + (it_ & 3) * STGSZ,          \
                  acc, wm, wn, lane);                                        \
        if (it_ + 3 < (KI)) ISSUE(it_ + 3);                                  \
        CP_COMMIT();                                                         \
    }

// ---------------------------------------------------------------------------
// k_scores: S[b,n,m] = sum_c ET[n,c] * QT[m,c].  grid (8,8,16), 128 thr
// ---------------------------------------------------------------------------
__global__ void __launch_bounds__(128, 2) k_scores(const __half* __restrict__ ET,
                                                   const __half* __restrict__ QT,
                                                   float* __restrict__ S) {
    GEMM_PRE();
    int b = blockIdx.z;
    int n0 = blockIdx.y * 128, m0 = blockIdx.x * 128;
    const __half* arow = ET + (size_t)b * N_ * C_ + (size_t)(n0 + t) * C_;
    const __half* brow = QT + (size_t)b * N_ * C_ + (size_t)(m0 + t) * C_;
    float* Sb = S + (size_t)b * N_ * N_;

    auto issue = [&](int it) {
        uint32_t da = sAs + (it & 3) * STGSZ + t * 48;
        uint32_t db = sBs + (it & 3) * STGSZ + t * 48;
        const __half* pa = arow + it * 16;
        const __half* pb = brow + it * 16;
        cpa16(da, pa, 16); cpa16(da + 16, pa + 8, 16);
        cpa16(db, pb, 16); cpa16(db + 16, pb + 8, 16);
    };

    ZERO_ACC(acc);
    GEMM_PIPE(C_ / 16, issue, acc);

#pragma unroll
    for (int mt = 0; mt < 4; ++mt)
#pragma unroll
        for (int nt = 0; nt < 8; ++nt) {
            int row = n0 + wm + mt * 16 + g;
            int col = m0 + wn + nt * 8 + tg * 2;
            *(float2*)(Sb + (size_t)row * N_ + col)       = make_float2(acc[mt][nt][0], acc[mt][nt][1]);
            *(float2*)(Sb + (size_t)(row + 8) * N_ + col) = make_float2(acc[mt][nt][2], acc[mt][nt][3]);
        }
}

// ---------------------------------------------------------------------------
// Row softmax: read fp32 scores, write fp16 probs. grid B_*N_, 256 thr
// ---------------------------------------------------------------------------
__global__ void __launch_bounds__(256) k_softmaxP(const float* __restrict__ S,
                                                  __half* __restrict__ P) {
    const float* row = S + (size_t)blockIdx.x * N_;
    __half*      out = P + (size_t)blockIdx.x * N_;
    int t = threadIdx.x;
    float4 v = *(const float4*)(row + 4 * t);
    __shared__ float red[8];

    float m = fmaxf(fmaxf(v.x, v.y), fmaxf(v.z, v.w));
#pragma unroll
    for (int o = 16; o; o >>= 1) m = fmaxf(m, __shfl_xor_sync(0xffffffffu, m, o));
    if ((t & 31) == 0) red[t >> 5] = m;
    __syncthreads();
    float mx = red[0];
#pragma unroll
    for (int i = 1; i < 8; ++i) mx = fmaxf(mx, red[i]);
    __syncthreads();

    v.x = __expf(v.x - mx); v.y = __expf(v.y - mx);
    v.z = __expf(v.z - mx); v.w = __expf(v.w - mx);
    float s = v.x + v.y + v.z + v.w;
#pragma unroll
    for (int o = 16; o; o >>= 1) s += __shfl_xor_sync(0xffffffffu, s, o);
    if ((t & 31) == 0) red[t >> 5] = s;
    __syncthreads();
    float tot = red[0];
#pragma unroll
    for (int i = 1; i < 8; ++i) tot += red[i];
    float inv = 1.f / tot;

    __half2 lo = __floats2half2_rn(v.x * inv, v.y * inv);
    __half2 hi = __floats2half2_rn(v.z * inv, v.w * inv);
    *(__half2*)(out + 4 * t)     = lo;
    *(__half2*)(out + 4 * t + 2) = hi;
}

// ---------------------------------------------------------------------------
// k_attmm: O[b,c,n] = sum_m Q16[c,m] * P[n,m].  grid (8,4,16)
// ---------------------------------------------------------------------------
__global__ void __launch_bounds__(128, 2) k_attmm(const __half* __restrict__ Q16,
                                                  const __half* __restrict__ P,
                                                  float* __restrict__ O) {
    GEMM_PRE();
    int b = blockIdx.z;
    int c0 = blockIdx.y * 128, n0 = blockIdx.x * 128;
    const __half* arow = Q16 + (size_t)b * C_ * N_ + (size_t)(c0 + t) * N_;
    const __half* brow = P   + (size_t)b * N_ * N_ + (size_t)(n0 + t) * N_;
    float* Ob = O + (size_t)b * C_ * N_;

    auto issue = [&](int it) {
        uint32_t da = sAs + (it & 3) * STGSZ + t * 48;
        uint32_t db = sBs + (it & 3) * STGSZ + t * 48;
        const __half* pa = arow + it * 16;
        const __half* pb = brow + it * 16;
        cpa16(da, pa, 16); cpa16(da + 16, pa + 8, 16);
        cpa16(db, pb, 16); cpa16(db + 16, pb + 8, 16);
    };

    ZERO_ACC(acc);
    GEMM_PIPE(N_ / 16, issue, acc);

#pragma unroll
    for (int mt = 0; mt < 4; ++mt)
#pragma unroll
        for (int nt = 0; nt < 8; ++nt) {
            int row = c0 + wm + mt * 16 + g;
            int col = n0 + wn + nt * 8 + tg * 2;
            *(float2*)(Ob + (size_t)row * N_ + col)       = make_float2(acc[mt][nt][0], acc[mt][nt][1]);
            *(float2*)(Ob + (size_t)(row + 8) * N_ + col) = make_float2(acc[mt][nt][2], acc[mt][nt][3]);
        }
}

// ---------------------------------------------------------------------------
// k_gemmRU: fused reset+update GEMM, M=1024, B=[xT;hT] rows=p. grid (8,8,16)
// ---------------------------------------------------------------------------
__global__ void __launch_bounds__(128, 2) k_gemmRU(const __half* __restrict__ Wru,
                                                   const __half* __restrict__ xT,
                                                   const __half* __restrict__ hT,
                                                   const float* __restrict__ b_r,
                                                   const float* __restrict__ b_u,
                                                   float* __restrict__ R,
                                                   float* __restrict__ U) {
    GEMM_PRE();
    int b = blockIdx.z;
    int co0 = blockIdx.y * 128, p0 = blockIdx.x * 128;
    const __half* arow = Wru + (size_t)(co0 + t) * (2 * C_);
    const __half* xrow = xT + (size_t)b * N_ * C_ + (size_t)(p0 + t) * C_;
    const __half* hrow = hT + (size_t)b * N_ * C_ + (size_t)(p0 + t) * C_;

    auto issue = [&](int it) {
        uint32_t da = sAs + (it & 3) * STGSZ + t * 48;
        uint32_t db = sBs + (it & 3) * STGSZ + t * 48;
        int ci0 = it * 16;
        const __half* pa = arow + ci0;
        const __half* pb = (ci0 < C_) ? (xrow + ci0) : (hrow + ci0 - C_);
        cpa16(da, pa, 16); cpa16(da + 16, pa + 8, 16);
        cpa16(db, pb, 16); cpa16(db + 16, pb + 8, 16);
    };

    ZERO_ACC(acc);
    GEMM_PIPE((2 * C_) / 16, issue, acc);

    bool isR = co0 < C_;
    float* dst = (isR ? R : U) + (size_t)b * C_ * N_;
    int rbase = isR ? co0 : (co0 - C_);
    const float* bias = isR ? b_r : b_u;
#pragma unroll
    for (int mt = 0; mt < 4; ++mt)
#pragma unroll
        for (int nt = 0; nt < 8; ++nt) {
            int row = rbase + wm + mt * 16 + g;
            int col = p0 + wn + nt * 8 + tg * 2;
            float bv0 = bias[row], bv1 = bias[row + 8];
            float o0 = 1.f / (1.f + __expf(-(acc[mt][nt][0] + bv0)));
            float o1 = 1.f / (1.f + __expf(-(acc[mt][nt][1] + bv0)));
            float o2 = 1.f / (1.f + __expf(-(acc[mt][nt][2] + bv1)));
            float o3 = 1.f / (1.f + __expf(-(acc[mt][nt][3] + bv1)));
            *(float2*)(dst + (size_t)row * N_ + col)       = make_float2(o0, o1);
            *(float2*)(dst + (size_t)(row + 8) * N_ + col) = make_float2(o2, o3);
        }
}

// ---------------------------------------------------------------------------
// k_gemmCAND: c = tanh(Wc @ [x ; r*h] + b), B rows=p. grid (8,4,16)
// ---------------------------------------------------------------------------
__global__ void __launch_bounds__(128, 2) k_gemmCAND(const __half* __restrict__ Wc,
                                                     const __half* __restrict__ xT,
                                                     const __half* __restrict__ rhT,
                                                     const float* __restrict__ bias,
                                                     float* __restrict__ Y) {
    GEMM_PRE();
    int b = blockIdx.z;
    int co0 = blockIdx.y * 128, p0 = blockIdx.x * 128;
    const __half* arow = Wc + (size_t)(co0 + t) * (2 * C_);
    const __half* xrow  = xT  + (size_t)b * N_ * C_ + (size_t)(p0 + t) * C_;
    const __half* rhrow = rhT + (size_t)b * N_ * C_ + (size_t)(p0 + t) * C_;
    float* Yb = Y + (size_t)b * C_ * N_;

    auto issue = [&](int it) {
        uint32_t da = sAs + (it & 3) * STGSZ + t * 48;
        uint32_t db = sBs + (it & 3) * STGSZ + t * 48;
        int ci0 = it * 16;
        const __half* pa = arow + ci0;
        const __half* pb = (ci0 < C_) ? (xrow + ci0) : (rhrow + ci0 - C_);
        cpa16(da, pa, 16); cpa16(da + 16, pa + 8, 16);
        cpa16(db, pb, 16); cpa16(db + 16, pb + 8, 16);
    };

    ZERO_ACC(acc);
    GEMM_PIPE((2 * C_) / 16, issue, acc);

#pragma unroll
    for (int mt = 0; mt < 4; ++mt)
#pragma unroll
        for (int nt = 0; nt < 8; ++nt) {
            int row = co0 + wm + mt * 16 + g;
            int col = p0 + wn + nt * 8 + tg * 2;
            float bv0 = bias[row], bv1 = bias[row + 8];
            *(float2*)(Yb + (size_t)row * N_ + col) =
                make_float2(tanhf(acc[mt][nt][0] + bv0), tanhf(acc[mt][nt][1] + bv0));
            *(float2*)(Yb + (size_t)(row + 8) * N_ + col) =
                make_float2(tanhf(acc[mt][nt][2] + bv1), tanhf(acc[mt][nt][3] + bv1));
        }
}

// ---------------------------------------------------------------------------
// k_conv3: 3x3 conv pad 1, implicit GEMM K=9216. B = shifted rows of the
// transposed [p][c] fp16 image (contiguous; OOB rows zero-filled). grid (8,4,16)
// ---------------------------------------------------------------------------
__global__ void __launch_bounds__(128, 2) k_conv3(const __half* __restrict__ Wt,
                                                  const __half* __restrict__ x0T,
                                                  const __half* __restrict__ x1T,
                                                  const float* __restrict__ bias,
                                                  float* __restrict__ Y) {
    GEMM_PRE();
    int b = blockIdx.z;
    int co0 = blockIdx.y * 128, p0 = blockIdx.x * 128;
    const __half* x0b = x0T + (size_t)b * N_ * C_;
    const __half* x1b = x1T + (size_t)b * N_ * C_;
    float* Yb = Y + (size_t)b * C_ * N_;

    int p = p0 + t;
    int py = p >> 5, px = p & 31;

    auto issue = [&](int it) {
        int tap = it >> 6, ci0 = (it & 63) * 16;
        uint32_t da = sAs + (it & 3) * STGSZ + t * 48;
        uint32_t db = sBs + (it & 3) * STGSZ + t * 48;
        const __half* pa = Wt + ((size_t)tap * C_ + co0 + t) * (2 * C_) + ci0;
        cpa16(da, pa, 16); cpa16(da + 16, pa + 8, 16);

        int dy = tap / 3 - 1, dx = tap % 3 - 1;
        int y = py + dy, x = px + dx;
        bool ok = ((unsigned)y < HW) && ((unsigned)x < HW);
        int pp = ok ? (y * HW + x) : 0;
        const __half* pb = (ci0 < C_) ? (x0b + (size_t)pp * C_ + ci0)
                                      : (x1b + (size_t)pp * C_ + ci0 - C_);
        uint32_t sz = ok ? 16u : 0u;
        cpa16(db, pb, sz); cpa16(db + 16, pb + 8, sz);
    };

    ZERO_ACC(acc);
    GEMM_PIPE(9 * (2 * C_) / 16, issue, acc);

#pragma unroll
    for (int mt = 0; mt < 4; ++mt)
#pragma unroll
        for (int nt = 0; nt < 8; ++nt) {
            int row = co0 + wm + mt * 16 + g;
            int col = p0 + wn + nt * 8 + tg * 2;
            float bv0 = bias[row], bv1 = bias[row + 8];
            *(float2*)(Yb + (size_t)row * N_ + col)       = make_float2(acc[mt][nt][0] + bv0, acc[mt][nt][1] + bv0);
            *(float2*)(Yb + (size_t)(row + 8) * N_ + col) = make_float2(acc[mt][nt][2] + bv1, acc[mt][nt][3] + bv1);
        }
}

// ---------------------------------------------------------------------------
// Transpose/convert kernels. grid (N_/32, C_/32, B_), block (32,8)
// ---------------------------------------------------------------------------
__global__ void k_tr2(const float* __restrict__ in, __half* __restrict__ outN,
                      __half* __restrict__ outT) {
    __shared__ float tile[32][33];
    int b = blockIdx.z;
    const float* ib = in + (size_t)b * C_ * N_;
    __half* on = outN + (size_t)b * C_ * N_;
    __half* ot = outT + (size_t)b * N_ * C_;
    int n0 = blockIdx.x * 32, c0 = blockIdx.y * 32;
    int tx = threadIdx.x, ty = threadIdx.y;
#pragma unroll
    for (int j = 0; j < 4; ++j) {
        float v = ib[(size_t)(c0 + ty + 8 * j) * N_ + n0 + tx];
        tile[ty + 8 * j][tx] = v;
        on[(size_t)(c0 + ty + 8 * j) * N_ + n0 + tx] = __float2half_rn(v);
    }
    __syncthreads();
#pragma unroll
    for (int j = 0; j < 4; ++j)
        ot[(size_t)(n0 + ty + 8 * j) * C_ + c0 + tx] = __float2half_rn(tile[tx][ty + 8 * j]);
}

__global__ void k_trh(const float* __restrict__ in, __half* __restrict__ outT) {
    __shared__ float tile[32][33];
    int b = blockIdx.z;
    const float* ib = in + (size_t)b * C_ * N_;
    __half* ot = outT + (size_t)b * N_ * C_;
    int n0 = blockIdx.x * 32, c0 = blockIdx.y * 32;
    int tx = threadIdx.x, ty = threadIdx.y;
#pragma unroll
    for (int j = 0; j < 4; ++j)
        tile[ty + 8 * j][tx] = ib[(size_t)(c0 + ty + 8 * j) * N_ + n0 + tx];
    __syncthreads();
#pragma unroll
    for (int j = 0; j < 4; ++j)
        ot[(size_t)(n0 + ty + 8 * j) * C_ + c0 + tx] = __float2half_rn(tile[tx][ty + 8 * j]);
}

__global__ void k_rh(const float* __restrict__ r, const float* __restrict__ h,
                     __half* __restrict__ outT) {
    __shared__ float tile[32][33];
    int b = blockIdx.z;
    const float* rb = r + (size_t)b * C_ * N_;
    const float* hb = h + (size_t)b * C_ * N_;
    __half* ot = outT + (size_t)b * N_ * C_;
    int n0 = blockIdx.x * 32, c0 = blockIdx.y * 32;
    int tx = threadIdx.x, ty = threadIdx.y;
#pragma unroll
    for (int j = 0; j < 4; ++j) {
        size_t idx = (size_t)(c0 + ty + 8 * j) * N_ + n0 + tx;
        tile[ty + 8 * j][tx] = rb[idx] * hb[idx];
    }
    __syncthreads();
#pragma unroll
    for (int j = 0; j < 4; ++j)
        ot[(size_t)(n0 + ty + 8 * j) * C_ + c0 + tx] = __float2half_rn(tile[tx][ty + 8 * j]);
}

// ---------------------------------------------------------------------------
// Prep + elementwise kernels
// ---------------------------------------------------------------------------
__global__ void k_wt16(const float* __restrict__ w, __half* __restrict__ wt) {
    size_t i = (size_t)blockIdx.x * 256 + threadIdx.x;
    if (i >= WTSZ) return;
    int ci  = (int)(i % (2 * C_));
    int co  = (int)((i / (2 * C_)) % C_);
    int tap = (int)(i / ((size_t)C_ * 2 * C_));
    wt[i] = __float2half_rn(w[((size_t)co * (2 * C_) + ci) * 9 + tap]);
}

__global__ void k_wru16(const float* __restrict__ wr, const float* __restrict__ wu,
                        __half* __restrict__ o) {
    size_t i = (size_t)blockIdx.x * 256 + threadIdx.x;
    size_t half = (size_t)C_ * 2 * C_;
    if (i < half) o[i] = __float2half_rn(wr[i]);
    else if (i < 2 * half) o[i] = __float2half_rn(wu[i - half]);
}

__global__ void k_wc16(const float* __restrict__ w, __half* __restrict__ o) {
    size_t i = (size_t)blockIdx.x * 256 + threadIdx.x;
    if (i < (size_t)C_ * 2 * C_) o[i] = __float2half_rn(w[i]);
}

__global__ void k_init(const float* __restrict__ a, const float* __restrict__ b,
                       const float* __restrict__ c) {
    size_t i = ((size_t)blockIdx.x * 256 + threadIdx.x) * 4;
    *(float4*)(g_ex + i) = *(const float4*)(a + i);
    *(float4*)(g_q  + i) = *(const float4*)(b + i);
    *(float4*)(g_q1 + i) = *(const float4*)(c + i);
}

__global__ void k_gruout(float* __restrict__ h, const float* __restrict__ u,
                         const float* __restrict__ c) {
    size_t i = ((size_t)blockIdx.x * 256 + threadIdx.x) * 4;
    float4 hv = *(float4*)(h + i);
    float4 uv = *(const float4*)(u + i);
    float4 cv = *(const float4*)(c + i);
    hv.x = hv.x * (1.f - uv.x) + cv.x * uv.x;
    hv.y = hv.y * (1.f - uv.y) + cv.y * uv.y;
    hv.z = hv.z * (1.f - uv.z) + cv.z * uv.z;
    hv.w = hv.w * (1.f - uv.w) + cv.w * uv.w;
    *(float4*)(h + i) = hv;
}

// ---------------------------------------------------------------------------
// Host orchestration
// ---------------------------------------------------------------------------
extern "C" void kernel_launch(void* const* d_in, const int* in_sizes, int n_in,
                              void* d_out, int out_size) {
    const float* in1      = (const float*)d_in[0];
    const float* in2      = (const float*)d_in[1];
    const float* in3      = (const float*)d_in[2];
    const float* w_fusion = (const float*)d_in[3];
    const float* b_fusion = (const float*)d_in[4];
    const float* w_out    = (const float*)d_in[5];
    const float* b_out    = (const float*)d_in[6];
    const float* w_reset  = (const float*)d_in[7];
    const float* b_reset  = (const float*)d_in[8];
    const float* w_update = (const float*)d_in[9];
    const float* b_update = (const float*)d_in[10];
    const float* w_cand   = (const float*)d_in[11];
    const float* b_cand   = (const float*)d_in[12];
    float* out = (float*)d_out;

    cudaFuncSetAttribute(k_scores,   cudaFuncAttributeMaxDynamicSharedMemorySize, SMEM_DYN);
    cudaFuncSetAttribute(k_attmm,    cudaFuncAttributeMaxDynamicSharedMemorySize, SMEM_DYN);
    cudaFuncSetAttribute(k_gemmRU,   cudaFuncAttributeMaxDynamicSharedMemorySize, SMEM_DYN);
    cudaFuncSetAttribute(k_gemmCAND, cudaFuncAttributeMaxDynamicSharedMemorySize, SMEM_DYN);
    cudaFuncSetAttribute(k_conv3,    cudaFuncAttributeMaxDynamicSharedMemorySize, SMEM_DYN);

    float *S, *O1, *O2, *a, *ex, *q, *q1, *r, *u, *c;
    __half *P16, *ex16, *q16, *q116, *exT, *qT, *q1T;
    __half *O1T, *O2T, *aT, *rhT, *in1T, *in2T, *in3T;
    __half *wf16, *wo16, *wru16, *wc16;
    cudaGetSymbolAddress((void**)&S,    g_S);
    cudaGetSymbolAddress((void**)&O1,   g_O1);
    cudaGetSymbolAddress((void**)&O2,   g_O2);
    cudaGetSymbolAddress((void**)&a,    g_a);
    cudaGetSymbolAddress((void**)&ex,   g_ex);
    cudaGetSymbolAddress((void**)&q,    g_q);
    cudaGetSymbolAddress((void**)&q1,   g_q1);
    cudaGetSymbolAddress((void**)&r,    g_r);
    cudaGetSymbolAddress((void**)&u,    g_u);
    cudaGetSymbolAddress((void**)&c,    g_c);
    cudaGetSymbolAddress((void**)&P16,  g_P16);
    cudaGetSymbolAddress((void**)&ex16, g_ex16);
    cudaGetSymbolAddress((void**)&q16,  g_q16);
    cudaGetSymbolAddress((void**)&q116, g_q116);
    cudaGetSymbolAddress((void**)&exT,  g_exT16);
    cudaGetSymbolAddress((void**)&qT,   g_qT16);
    cudaGetSymbolAddress((void**)&q1T,  g_q1T16);
    cudaGetSymbolAddress((void**)&O1T,  g_O1T16);
    cudaGetSymbolAddress((void**)&O2T,  g_O2T16);
    cudaGetSymbolAddress((void**)&aT,   g_aT16);
    cudaGetSymbolAddress((void**)&rhT,  g_rhT16);
    cudaGetSymbolAddress((void**)&in1T, g_in1T16);
    cudaGetSymbolAddress((void**)&in2T, g_in2T16);
    cudaGetSymbolAddress((void**)&in3T, g_in3T16);
    cudaGetSymbolAddress((void**)&wf16, g_wf16);
    cudaGetSymbolAddress((void**)&wo16, g_wo16);
    cudaGetSymbolAddress((void**)&wru16, g_wru16);
    cudaGetSymbolAddress((void**)&wc16, g_wc16);

    const int EWG = (int)(TSZ / 4 / 256);
    const int WTG = (int)((WTSZ + 255) / 256);
    const int RUG = (int)(((size_t)2 * C_ * 2 * C_ + 255) / 256);
    const int WCG = (int)(((size_t)C_ * 2 * C_ + 255) / 256);

    k_init<<<EWG, 256>>>(in1, in2, in3);
    k_wt16<<<WTG, 256>>>(w_fusion, wf16);
    k_wt16<<<WTG, 256>>>(w_out, wo16);
    k_wru16<<<RUG, 256>>>(w_reset, w_update, wru16);
    k_wc16<<<WCG, 256>>>(w_cand, wc16);

    dim3 trG(32, 16, B_), trB(32, 8);
    k_trh<<<trG, trB>>>(in1, in1T);
    k_trh<<<trG, trB>>>(in2, in2T);
    k_trh<<<trG, trB>>>(in3, in3T);

    dim3 gSC(8, 8, B_);     // scores / RU (M=1024)
    dim3 gAT(8, 4, B_);     // attmm / conv3 / cand
    const int SMG = B_ * N_;

    float*  hs [3] = {ex, q, q1};
    __half* h16[3] = {ex16, q16, q116};
    __half* hT [3] = {exT, qT, q1T};

    for (int round = 0; round < 5; ++round) {
        k_tr2<<<trG, trB>>>(ex, ex16, exT);
        k_tr2<<<trG, trB>>>(q,  q16,  qT);
        k_tr2<<<trG, trB>>>(q1, q116, q1T);

        // per-state: attention pair -> fusion conv -> GRU update (fp32 state only)
        for (int s = 0; s < 3; ++s) {
            __half* meT = hT[s];
            __half* o1  = (s == 0) ? qT  : exT;   // first attention partner (T)
            __half* o1n = (s == 0) ? q16 : ex16;  // its normal mirror
            __half* o2  = (s == 2) ? qT  : q1T;   // second partner
            __half* o2n = (s == 2) ? q16 : q116;

            k_scores<<<gSC, 128, SMEM_DYN>>>(meT, o1, S);
            k_softmaxP<<<SMG, 256>>>(S, P16);
            k_attmm<<<gAT, 128, SMEM_DYN>>>(o1n, P16, O1);

            k_scores<<<gSC, 128, SMEM_DYN>>>(meT, o2, S);
            k_softmaxP<<<SMG, 256>>>(S, P16);
            k_attmm<<<gAT, 128, SMEM_DYN>>>(o2n, P16, O2);

            k_trh<<<trG, trB>>>(O1, O1T);
            k_trh<<<trG, trB>>>(O2, O2T);
            k_conv3<<<gAT, 128, SMEM_DYN>>>(wf16, O1T, O2T, b_fusion, a);

            k_trh<<<trG, trB>>>(a, aT);
            k_gemmRU<<<gSC, 128, SMEM_DYN>>>(wru16, aT, hT[s], b_reset, b_update, r, u);
            k_rh<<<trG, trB>>>(r, hs[s], rhT);
            k_gemmCAND<<<gAT, 128, SMEM_DYN>>>(wc16, aT, rhT, b_cand, c);
            k_gruout<<<EWG, 256>>>(hs[s], u, c);
        }
    }

    // final output convs: B = [stateT ; inT]
    k_trh<<<trG, trB>>>(ex, exT);
    k_trh<<<trG, trB>>>(q,  qT);
    k_trh<<<trG, trB>>>(q1, q1T);
    k_conv3<<<gAT, 128, SMEM_DYN>>>(wo16, exT, in1T, b_out, out);
    k_conv3<<<gAT, 128, SMEM_DYN>>>(wo16, qT,  in2T, b_out, out + TSZ);
    k_conv3<<<gAT, 128, SMEM_DYN>>>(wo16, q1T, in3T, b_out, out + 2 * TSZ);
}